// round 1
// baseline (speedup 1.0000x reference)
#include <cuda_runtime.h>
#include <math.h>

#define HIDDEN 256
#define BATCH  8
#define NA     2048
#define NB     2048

// Scratch for Q/K/V projections (16 MB each). Device globals are the allowed
// scratch mechanism (no cudaMalloc permitted).
__device__ float g_Q[(size_t)BATCH * NA * HIDDEN];
__device__ float g_K[(size_t)BATCH * NB * HIDDEN];
__device__ float g_V[(size_t)BATCH * NB * HIDDEN];

// ---------------------------------------------------------------------------
// Projection: out[row,h] = sum_k X[row,k] * W[h,k] + bias[h]   (NT SGEMM)
// grid.z encodes (which, batch): which 0=Q(A,Wq) 1=K(B,Wk) 2=V(B,Wv)
// ---------------------------------------------------------------------------
#define PJ_BM 64
#define PJ_BN 64
#define PJ_BK 32

__global__ __launch_bounds__(256) void proj_kernel(
    const float* __restrict__ A, const float* __restrict__ B,
    const float* __restrict__ Wq, const float* __restrict__ bq,
    const float* __restrict__ Wk, const float* __restrict__ bk,
    const float* __restrict__ Wv, const float* __restrict__ bv)
{
    __shared__ float Xs[PJ_BM][PJ_BK + 1];
    __shared__ float Ws[PJ_BN][PJ_BK + 1];

    const int z     = blockIdx.z;
    const int b     = z & 7;
    const int which = z >> 3;

    const float* X    = (which == 0) ? (A + (size_t)b * NA * HIDDEN)
                                     : (B + (size_t)b * NB * HIDDEN);
    const float* W    = (which == 0) ? Wq : (which == 1) ? Wk : Wv;
    const float* bias = (which == 0) ? bq : (which == 1) ? bk : bv;
    float* out = ((which == 0) ? g_Q : (which == 1) ? g_K : g_V)
                 + (size_t)b * 2048 * HIDDEN;

    const int r0 = blockIdx.x * PJ_BM;
    const int h0 = blockIdx.y * PJ_BN;
    const int tx = threadIdx.x, ty = threadIdx.y;
    const int tid = ty * 16 + tx;

    float acc[4][4] = {};

    for (int k0 = 0; k0 < HIDDEN; k0 += PJ_BK) {
        for (int i = tid; i < PJ_BM * PJ_BK; i += 256) {
            const int r = i >> 5;      // 0..63
            const int k = i & 31;      // 0..31
            Xs[r][k] = X[(size_t)(r0 + r) * HIDDEN + k0 + k];
            Ws[r][k] = W[(size_t)(h0 + r) * HIDDEN + k0 + k];
        }
        __syncthreads();

        #pragma unroll 8
        for (int k = 0; k < PJ_BK; k++) {
            float a[4], w[4];
            #pragma unroll
            for (int i = 0; i < 4; i++) a[i] = Xs[ty * 4 + i][k];
            #pragma unroll
            for (int j = 0; j < 4; j++) w[j] = Ws[tx * 4 + j][k];
            #pragma unroll
            for (int i = 0; i < 4; i++)
                #pragma unroll
                for (int j = 0; j < 4; j++)
                    acc[i][j] += a[i] * w[j];
        }
        __syncthreads();
    }

    #pragma unroll
    for (int i = 0; i < 4; i++) {
        const int r = r0 + ty * 4 + i;
        #pragma unroll
        for (int j = 0; j < 4; j++) {
            const int h = h0 + tx * 4 + j;
            out[(size_t)r * HIDDEN + h] = acc[i][j] + bias[h];
        }
    }
}

// ---------------------------------------------------------------------------
// Fused masked attention (flash-style, online softmax), fp32.
// One CTA: 64 Q rows of one batch. Loop over 32 KV tiles of 64 rows.
// Threads (16,16): S tile 4x4/thread; O tile 4 rows x 16 cols/thread.
// ---------------------------------------------------------------------------
#define FM 64
#define FN 64
#define QS_LD 257   // padded row stride (floats)
#define KS_LD 257
#define PS_LD 68

#define ATTN_SMEM_FLOATS (FM * QS_LD + FN * KS_LD + FN * HIDDEN + FM * PS_LD + FN)

__global__ __launch_bounds__(256, 1) void attn_kernel(
    const int* __restrict__ maskB, float* __restrict__ out)
{
    extern __shared__ float sm[];
    float* Qs  = sm;
    float* Ks  = Qs + FM * QS_LD;
    float* Vs  = Ks + FN * KS_LD;
    float* Ps  = Vs + FN * HIDDEN;
    float* Msk = Ps + FM * PS_LD;

    const int b  = blockIdx.y;
    const int q0 = blockIdx.x * FM;
    const int tx = threadIdx.x, ty = threadIdx.y;
    const int tid = ty * 16 + tx;

    const float* Q  = g_Q + (size_t)b * NA * HIDDEN;
    const float* K  = g_K + (size_t)b * NB * HIDDEN;
    const float* V  = g_V + (size_t)b * NB * HIDDEN;
    const int*   mk = maskB + b * NB;

    // Load Q tile (64 x 256) once, padded stride.
    for (int i = tid; i < FM * (HIDDEN / 4); i += 256) {
        const int r  = i >> 6;        // 0..63
        const int c4 = i & 63;        // 0..63  (float4 index)
        const float4 v = *(const float4*)&Q[(size_t)(q0 + r) * HIDDEN + c4 * 4];
        float* d = &Qs[r * QS_LD + c4 * 4];
        d[0] = v.x; d[1] = v.y; d[2] = v.z; d[3] = v.w;
    }

    float O[4][16];
    #pragma unroll
    for (int i = 0; i < 4; i++)
        #pragma unroll
        for (int c = 0; c < 16; c++) O[i][c] = 0.f;

    float mrow[4], lrow[4];
    #pragma unroll
    for (int i = 0; i < 4; i++) { mrow[i] = -1e30f; lrow[i] = 0.f; }

    const float scale = 0.0625f;  // 1/sqrt(256)

    for (int t = 0; t < NB / FN; t++) {
        const int n0 = t * FN;

        // Load K,V tiles + mask flags for this tile.
        for (int i = tid; i < FN * (HIDDEN / 4); i += 256) {
            const int r  = i >> 6;
            const int c4 = i & 63;
            const size_t g = (size_t)(n0 + r) * HIDDEN + c4 * 4;
            const float4 kv = *(const float4*)&K[g];
            float* dk = &Ks[r * KS_LD + c4 * 4];
            dk[0] = kv.x; dk[1] = kv.y; dk[2] = kv.z; dk[3] = kv.w;
            *(float4*)&Vs[r * HIDDEN + c4 * 4] = *(const float4*)&V[g];
        }
        if (tid < FN) Msk[tid] = (mk[n0 + tid] == 0) ? -1e30f : 0.f;
        __syncthreads();

        // S = Q K^T (4x4 per thread)
        float sacc[4][4] = {};
        #pragma unroll 8
        for (int k = 0; k < HIDDEN; k++) {
            float qa[4], kb[4];
            #pragma unroll
            for (int i = 0; i < 4; i++) qa[i] = Qs[(4 * ty + i) * QS_LD + k];
            #pragma unroll
            for (int j = 0; j < 4; j++) kb[j] = Ks[(4 * tx + j) * KS_LD + k];
            #pragma unroll
            for (int i = 0; i < 4; i++)
                #pragma unroll
                for (int j = 0; j < 4; j++)
                    sacc[i][j] += qa[i] * kb[j];
        }

        // Scale + mask, online softmax update.
        float s[4][4];
        #pragma unroll
        for (int i = 0; i < 4; i++)
            #pragma unroll
            for (int j = 0; j < 4; j++)
                s[i][j] = sacc[i][j] * scale + Msk[4 * tx + j];

        #pragma unroll
        for (int i = 0; i < 4; i++) {
            float tmax = fmaxf(fmaxf(s[i][0], s[i][1]), fmaxf(s[i][2], s[i][3]));
            #pragma unroll
            for (int off = 1; off < 16; off <<= 1)
                tmax = fmaxf(tmax, __shfl_xor_sync(0xffffffffu, tmax, off));

            const float mnew  = fmaxf(mrow[i], tmax);
            const float alpha = __expf(mrow[i] - mnew);
            float rsum = 0.f;
            #pragma unroll
            for (int j = 0; j < 4; j++) {
                const float p = __expf(s[i][j] - mnew);
                s[i][j] = p;
                rsum += p;
            }
            #pragma unroll
            for (int off = 1; off < 16; off <<= 1)
                rsum += __shfl_xor_sync(0xffffffffu, rsum, off);

            lrow[i] = lrow[i] * alpha + rsum;
            mrow[i] = mnew;
            #pragma unroll
            for (int c = 0; c < 16; c++) O[i][c] *= alpha;
            #pragma unroll
            for (int j = 0; j < 4; j++)
                Ps[(4 * ty + i) * PS_LD + 4 * tx + j] = s[i][j];
        }
        __syncthreads();

        // O += P @ V  (4 rows x 16 cols per thread)
        #pragma unroll 4
        for (int j = 0; j < FN; j++) {
            float pr[4];
            #pragma unroll
            for (int i = 0; i < 4; i++) pr[i] = Ps[(4 * ty + i) * PS_LD + j];
            const float* vrow = &Vs[j * HIDDEN + tx * 16];
            #pragma unroll
            for (int u = 0; u < 4; u++) {
                const float4 v4 = *(const float4*)&vrow[4 * u];
                #pragma unroll
                for (int i = 0; i < 4; i++) {
                    O[i][4 * u + 0] += pr[i] * v4.x;
                    O[i][4 * u + 1] += pr[i] * v4.y;
                    O[i][4 * u + 2] += pr[i] * v4.z;
                    O[i][4 * u + 3] += pr[i] * v4.w;
                }
            }
        }
        __syncthreads();
    }

    // Epilogue: divide by l, write out.
    #pragma unroll
    for (int i = 0; i < 4; i++) {
        const float inv = 1.f / lrow[i];
        const size_t row = (size_t)b * NA + (q0 + 4 * ty + i);
        #pragma unroll
        for (int u = 0; u < 4; u++) {
            float4 v;
            v.x = O[i][4 * u + 0] * inv;
            v.y = O[i][4 * u + 1] * inv;
            v.z = O[i][4 * u + 2] * inv;
            v.w = O[i][4 * u + 3] * inv;
            *(float4*)&out[row * HIDDEN + tx * 16 + 4 * u] = v;
        }
    }
}

// ---------------------------------------------------------------------------
extern "C" void kernel_launch(void* const* d_in, const int* in_sizes, int n_in,
                              void* d_out, int out_size)
{
    const float* A    = (const float*)d_in[0];
    const float* B    = (const float*)d_in[1];
    const int*   mask = (const int*)  d_in[2];
    const float* Wq   = (const float*)d_in[3];
    const float* bq   = (const float*)d_in[4];
    const float* Wk   = (const float*)d_in[5];
    const float* bk   = (const float*)d_in[6];
    const float* Wv   = (const float*)d_in[7];
    const float* bv   = (const float*)d_in[8];
    float* out = (float*)d_out;

    (void)in_sizes; (void)n_in; (void)out_size;

    // Opt-in to large dynamic smem for the attention kernel (idempotent).
    static const size_t attn_smem = (size_t)ATTN_SMEM_FLOATS * sizeof(float);
    cudaFuncSetAttribute(attn_kernel, cudaFuncAttributeMaxDynamicSharedMemorySize,
                         (int)attn_smem);

    dim3 pb(16, 16);
    dim3 pg(NA / PJ_BM, HIDDEN / PJ_BN, 3 * BATCH);
    proj_kernel<<<pg, pb>>>(A, B, Wq, bq, Wk, bk, Wv, bv);

    dim3 ab(16, 16);
    dim3 ag(NA / FM, BATCH);
    attn_kernel<<<ag, ab, attn_smem>>>(mask, out);
}

// round 2
// speedup vs baseline: 1.0071x; 1.0071x over previous
#include <cuda_runtime.h>
#include <math.h>

#define HIDDEN 256
#define BATCH  8
#define NA     2048
#define NB     2048

// Q,K stored TRANSPOSED in gmem: [b][h][n]  (k-major for the attention S-loop)
// V stored row-major: [b][n][h]
__device__ float g_Qt[(size_t)BATCH * HIDDEN * NA];
__device__ float g_Kt[(size_t)BATCH * HIDDEN * NB];
__device__ float g_V [(size_t)BATCH * NB * HIDDEN];

// ---------------------------------------------------------------------------
// f32x2 packed-math helpers (FFMA2 — ptxas never auto-generates these)
// ---------------------------------------------------------------------------
__device__ __forceinline__ unsigned long long dup_f2(float x) {
    unsigned long long r;
    asm("mov.b64 %0, {%1, %1};" : "=l"(r) : "f"(x));
    return r;
}
__device__ __forceinline__ void fma_f2(unsigned long long& d,
                                       unsigned long long a,
                                       unsigned long long b) {
    asm("fma.rn.f32x2 %0, %1, %2, %0;" : "+l"(d) : "l"(a), "l"(b));
}
__device__ __forceinline__ void mul_f2(unsigned long long& d,
                                       unsigned long long a) {
    asm("mul.rn.f32x2 %0, %0, %1;" : "+l"(d) : "l"(a));
}
__device__ __forceinline__ float2 unp_f2(unsigned long long v) {
    float2 f;
    asm("mov.b64 {%0, %1}, %2;" : "=f"(f.x), "=f"(f.y) : "l"(v));
    return f;
}

// ---------------------------------------------------------------------------
// Projection: out[n,h] = X[n,:] . W[h,:] + bias[h]
// k-major smem + packed FMA. Q,K written transposed ([h][n]); V row-major.
// grid.z = which*8 + b;  which: 0=Q(A,Wq), 1=K(B,Wk), 2=V(B,Wv)
// ---------------------------------------------------------------------------
#define PJ_BK 32

__global__ __launch_bounds__(256) void proj_kernel(
    const float* __restrict__ A, const float* __restrict__ B,
    const float* __restrict__ Wq, const float* __restrict__ bq,
    const float* __restrict__ Wk, const float* __restrict__ bk,
    const float* __restrict__ Wv, const float* __restrict__ bv)
{
    __shared__ float XsT[PJ_BK][64];   // [k][n-local]
    __shared__ float WsT[PJ_BK][64];   // [k][h-local]

    const int z     = blockIdx.z;
    const int b     = z & 7;
    const int which = z >> 3;

    const float* X    = (which == 0) ? (A + (size_t)b * NA * HIDDEN)
                                     : (B + (size_t)b * NB * HIDDEN);
    const float* W    = (which == 0) ? Wq : (which == 1) ? Wk : Wv;
    const float* bias = (which == 0) ? bq : (which == 1) ? bk : bv;

    const int r0 = blockIdx.x * 64;    // n block
    const int h0 = blockIdx.y * 64;    // h block
    const int tid = threadIdx.x;
    const int tx = tid & 15;
    const int ty = tid >> 4;

    unsigned long long acc2[2][4];
    #pragma unroll
    for (int i = 0; i < 2; i++)
        #pragma unroll
        for (int j = 0; j < 4; j++) acc2[i][j] = 0ull;

    const int lr = tid & 63;     // lane-row for transpose loads (conflict-free stores)
    const int cs = tid >> 6;     // 0..3

    for (int k0 = 0; k0 < HIDDEN; k0 += PJ_BK) {
        #pragma unroll
        for (int s = 0; s < 2; s++) {
            const int kl = cs * 8 + s * 4;
            const float4 xv = *(const float4*)&X[(size_t)(r0 + lr) * HIDDEN + k0 + kl];
            XsT[kl + 0][lr] = xv.x; XsT[kl + 1][lr] = xv.y;
            XsT[kl + 2][lr] = xv.z; XsT[kl + 3][lr] = xv.w;
            const float4 wv = *(const float4*)&W[(size_t)(h0 + lr) * HIDDEN + k0 + kl];
            WsT[kl + 0][lr] = wv.x; WsT[kl + 1][lr] = wv.y;
            WsT[kl + 2][lr] = wv.z; WsT[kl + 3][lr] = wv.w;
        }
        __syncthreads();

        #pragma unroll 8
        for (int k = 0; k < PJ_BK; k++) {
            const ulonglong2 xp = *(const ulonglong2*)&XsT[k][4 * ty];
            const float4 wv = *(const float4*)&WsT[k][4 * tx];
            const unsigned long long b0 = dup_f2(wv.x), b1 = dup_f2(wv.y),
                                     b2 = dup_f2(wv.z), b3 = dup_f2(wv.w);
            fma_f2(acc2[0][0], xp.x, b0); fma_f2(acc2[0][1], xp.x, b1);
            fma_f2(acc2[0][2], xp.x, b2); fma_f2(acc2[0][3], xp.x, b3);
            fma_f2(acc2[1][0], xp.y, b0); fma_f2(acc2[1][1], xp.y, b1);
            fma_f2(acc2[1][2], xp.y, b2); fma_f2(acc2[1][3], xp.y, b3);
        }
        __syncthreads();
    }

    // Unpack: row i (= 4ty+i), col j (= 4tx+j)
    float s[4][4];
    #pragma unroll
    for (int rp = 0; rp < 2; rp++)
        #pragma unroll
        for (int j = 0; j < 4; j++) {
            const float2 p = unp_f2(acc2[rp][j]);
            s[2 * rp + 0][j] = p.x;
            s[2 * rp + 1][j] = p.y;
        }

    if (which < 2) {
        // Transposed write: out_t[h][n], float4 along n
        float* out_t = ((which == 0) ? g_Qt : g_Kt) + (size_t)b * HIDDEN * 2048;
        #pragma unroll
        for (int j = 0; j < 4; j++) {
            const int h = h0 + 4 * tx + j;
            const float bb = bias[h];
            float4 o;
            o.x = s[0][j] + bb; o.y = s[1][j] + bb;
            o.z = s[2][j] + bb; o.w = s[3][j] + bb;
            *(float4*)&out_t[(size_t)h * 2048 + r0 + 4 * ty] = o;
        }
    } else {
        // Row-major write: out[n][h]
        float* out = g_V + (size_t)b * 2048 * HIDDEN;
        const float b0 = bias[h0 + 4 * tx + 0], b1 = bias[h0 + 4 * tx + 1];
        const float b2 = bias[h0 + 4 * tx + 2], b3 = bias[h0 + 4 * tx + 3];
        #pragma unroll
        for (int i = 0; i < 4; i++) {
            float4 o;
            o.x = s[i][0] + b0; o.y = s[i][1] + b1;
            o.z = s[i][2] + b2; o.w = s[i][3] + b3;
            *(float4*)&out[(size_t)(r0 + 4 * ty + i) * HIDDEN + h0 + 4 * tx] = o;
        }
    }
}

// ---------------------------------------------------------------------------
// Fused masked attention, flash-style online softmax, fp32 with f32x2 FMA.
// BLOCK_M=64 q rows / CTA, BLOCK_N=64 kv rows / tile.
// smem: QsT[k=256][64], KsT[256][64], Vs[64][256], Ps[64][68], Msk[64]
// ---------------------------------------------------------------------------
#define FM 64
#define FN 64
#define PS_LD 68

#define ATTN_SMEM_FLOATS (HIDDEN * FM + HIDDEN * FN + FN * HIDDEN + FM * PS_LD + FN)

__global__ __launch_bounds__(256, 1) void attn_kernel(
    const int* __restrict__ maskB, float* __restrict__ out)
{
    extern __shared__ float sm[];
    float* QsT = sm;                        // [256][64]
    float* KsT = QsT + HIDDEN * FM;         // [256][64]
    float* Vs  = KsT + HIDDEN * FN;         // [64][256]
    float* Ps  = Vs + FN * HIDDEN;          // [64][68]
    float* Msk = Ps + FM * PS_LD;           // [64]

    const int b  = blockIdx.y;
    const int q0 = blockIdx.x * FM;
    const int tid = threadIdx.x;
    const int tx = tid & 15;
    const int ty = tid >> 4;

    const float* Qt = g_Qt + (size_t)b * HIDDEN * NA;
    const float* Kt = g_Kt + (size_t)b * HIDDEN * NB;
    const float* V  = g_V  + (size_t)b * NB * HIDDEN;
    const int*   mk = maskB + b * NB;

    // Load Q tile, already k-major in gmem: QsT[h][m] <- Qt[h][q0+m]
    for (int i = tid; i < HIDDEN * (FM / 4); i += 256) {
        const int h  = i >> 4;        // 0..255
        const int fc = i & 15;        // float4 col
        const float4 v = *(const float4*)&Qt[(size_t)h * 2048 + q0 + 4 * fc];
        *(float4*)&QsT[h * FM + 4 * fc] = v;
    }

    unsigned long long O2[4][8];
    #pragma unroll
    for (int i = 0; i < 4; i++)
        #pragma unroll
        for (int c = 0; c < 8; c++) O2[i][c] = 0ull;

    float mrow[4], lrow[4];
    #pragma unroll
    for (int i = 0; i < 4; i++) { mrow[i] = -1e30f; lrow[i] = 0.f; }

    const float scale = 0.0625f;  // 1/sqrt(256)

    for (int t = 0; t < NB / FN; t++) {
        const int n0 = t * FN;

        // K tile (k-major in gmem) and V tile (row-major)
        for (int i = tid; i < HIDDEN * (FN / 4); i += 256) {
            const int h  = i >> 4;
            const int fc = i & 15;
            const float4 v = *(const float4*)&Kt[(size_t)h * 2048 + n0 + 4 * fc];
            *(float4*)&KsT[h * FN + 4 * fc] = v;
        }
        for (int i = tid; i < FN * (HIDDEN / 4); i += 256) {
            const int r  = i >> 6;
            const int fc = i & 63;
            const float4 v = *(const float4*)&V[(size_t)(n0 + r) * HIDDEN + 4 * fc];
            *(float4*)&Vs[r * HIDDEN + 4 * fc] = v;
        }
        if (tid < FN) Msk[tid] = (mk[n0 + tid] == 0) ? -1e30f : 0.f;
        __syncthreads();

        // S = Q K^T : rows packed in pairs, 8 FFMA2 per k per thread
        unsigned long long sacc2[2][4];
        #pragma unroll
        for (int rp = 0; rp < 2; rp++)
            #pragma unroll
            for (int j = 0; j < 4; j++) sacc2[rp][j] = 0ull;

        #pragma unroll 8
        for (int k = 0; k < HIDDEN; k++) {
            const ulonglong2 qp = *(const ulonglong2*)&QsT[k * FM + 4 * ty];
            const float4 kv = *(const float4*)&KsT[k * FN + 4 * tx];
            const unsigned long long b0 = dup_f2(kv.x), b1 = dup_f2(kv.y),
                                     b2 = dup_f2(kv.z), b3 = dup_f2(kv.w);
            fma_f2(sacc2[0][0], qp.x, b0); fma_f2(sacc2[0][1], qp.x, b1);
            fma_f2(sacc2[0][2], qp.x, b2); fma_f2(sacc2[0][3], qp.x, b3);
            fma_f2(sacc2[1][0], qp.y, b0); fma_f2(sacc2[1][1], qp.y, b1);
            fma_f2(sacc2[1][2], qp.y, b2); fma_f2(sacc2[1][3], qp.y, b3);
        }

        // Unpack, scale + mask
        float s[4][4];
        #pragma unroll
        for (int rp = 0; rp < 2; rp++)
            #pragma unroll
            for (int j = 0; j < 4; j++) {
                const float2 p = unp_f2(sacc2[rp][j]);
                s[2 * rp + 0][j] = p.x;
                s[2 * rp + 1][j] = p.y;
            }
        #pragma unroll
        for (int i = 0; i < 4; i++)
            #pragma unroll
            for (int j = 0; j < 4; j++)
                s[i][j] = s[i][j] * scale + Msk[4 * tx + j];

        // Online softmax per row (rows split over tx half-warps)
        #pragma unroll
        for (int i = 0; i < 4; i++) {
            float tmax = fmaxf(fmaxf(s[i][0], s[i][1]), fmaxf(s[i][2], s[i][3]));
            #pragma unroll
            for (int off = 1; off < 16; off <<= 1)
                tmax = fmaxf(tmax, __shfl_xor_sync(0xffffffffu, tmax, off));

            const float mnew  = fmaxf(mrow[i], tmax);
            const float alpha = __expf(mrow[i] - mnew);
            float rsum = 0.f;
            #pragma unroll
            for (int j = 0; j < 4; j++) {
                const float p = __expf(s[i][j] - mnew);
                s[i][j] = p;
                rsum += p;
            }
            #pragma unroll
            for (int off = 1; off < 16; off <<= 1)
                rsum += __shfl_xor_sync(0xffffffffu, rsum, off);

            lrow[i] = lrow[i] * alpha + rsum;
            mrow[i] = mnew;

            const unsigned long long av = dup_f2(alpha);
            #pragma unroll
            for (int c = 0; c < 8; c++) mul_f2(O2[i][c], av);

            #pragma unroll
            for (int j = 0; j < 4; j++)
                Ps[(4 * ty + i) * PS_LD + 4 * tx + j] = s[i][j];
        }
        __syncthreads();

        // O += P @ V  (4 rows x 16 cols as 8 f32x2 pairs per row)
        #pragma unroll 4
        for (int j = 0; j < FN; j++) {
            const unsigned long long a0 = dup_f2(Ps[(4 * ty + 0) * PS_LD + j]);
            const unsigned long long a1 = dup_f2(Ps[(4 * ty + 1) * PS_LD + j]);
            const unsigned long long a2 = dup_f2(Ps[(4 * ty + 2) * PS_LD + j]);
            const unsigned long long a3 = dup_f2(Ps[(4 * ty + 3) * PS_LD + j]);
            const float* vrow = &Vs[j * HIDDEN + tx * 16];
            const ulonglong2 v0 = *(const ulonglong2*)&vrow[0];
            const ulonglong2 v1 = *(const ulonglong2*)&vrow[4];
            const ulonglong2 v2 = *(const ulonglong2*)&vrow[8];
            const ulonglong2 v3 = *(const ulonglong2*)&vrow[12];
            const unsigned long long vp[8] = {v0.x, v0.y, v1.x, v1.y,
                                              v2.x, v2.y, v3.x, v3.y};
            #pragma unroll
            for (int c = 0; c < 8; c++) {
                fma_f2(O2[0][c], a0, vp[c]);
                fma_f2(O2[1][c], a1, vp[c]);
                fma_f2(O2[2][c], a2, vp[c]);
                fma_f2(O2[3][c], a3, vp[c]);
            }
        }
        __syncthreads();
    }

    // Epilogue: divide by l, write out (cols = tx*16 + 2c + {0,1})
    #pragma unroll
    for (int i = 0; i < 4; i++) {
        const float inv = 1.f / lrow[i];
        const size_t row = (size_t)b * NA + (q0 + 4 * ty + i);
        #pragma unroll
        for (int u = 0; u < 4; u++) {
            const float2 pa = unp_f2(O2[i][2 * u + 0]);
            const float2 pb = unp_f2(O2[i][2 * u + 1]);
            float4 o;
            o.x = pa.x * inv; o.y = pa.y * inv;
            o.z = pb.x * inv; o.w = pb.y * inv;
            *(float4*)&out[row * HIDDEN + tx * 16 + 4 * u] = o;
        }
    }
}

// ---------------------------------------------------------------------------
extern "C" void kernel_launch(void* const* d_in, const int* in_sizes, int n_in,
                              void* d_out, int out_size)
{
    const float* A    = (const float*)d_in[0];
    const float* B    = (const float*)d_in[1];
    const int*   mask = (const int*)  d_in[2];
    const float* Wq   = (const float*)d_in[3];
    const float* bq   = (const float*)d_in[4];
    const float* Wk   = (const float*)d_in[5];
    const float* bk   = (const float*)d_in[6];
    const float* Wv   = (const float*)d_in[7];
    const float* bv   = (const float*)d_in[8];
    float* out = (float*)d_out;

    (void)in_sizes; (void)n_in; (void)out_size;

    static const size_t attn_smem = (size_t)ATTN_SMEM_FLOATS * sizeof(float);
    cudaFuncSetAttribute(attn_kernel, cudaFuncAttributeMaxDynamicSharedMemorySize,
                         (int)attn_smem);

    dim3 pg(NA / 64, HIDDEN / 64, 3 * BATCH);
    proj_kernel<<<pg, 256>>>(A, B, Wq, bq, Wk, bk, Wv, bv);

    dim3 ag(NA / FM, BATCH);
    attn_kernel<<<ag, 256, attn_smem>>>(mask, out);
}

// round 3
// speedup vs baseline: 1.0074x; 1.0002x over previous
#include <cuda_runtime.h>
#include <math.h>

#define HIDDEN 256
#define BATCH  8
#define NA     2048
#define NB     2048

// Q,K stored TRANSPOSED in gmem: [b][h][n]  (k-major for the attention S-loop)
// V stored row-major: [b][n][h]
__device__ float g_Qt[(size_t)BATCH * HIDDEN * NA];
__device__ float g_Kt[(size_t)BATCH * HIDDEN * NB];
__device__ float g_V [(size_t)BATCH * NB * HIDDEN];

// ---------------------------------------------------------------------------
// f32x2 packed-math helpers (FFMA2 — ptxas never auto-generates these)
// ---------------------------------------------------------------------------
__device__ __forceinline__ unsigned long long dup_f2(float x) {
    unsigned long long r;
    asm("mov.b64 %0, {%1, %1};" : "=l"(r) : "f"(x));
    return r;
}
__device__ __forceinline__ void fma_f2(unsigned long long& d,
                                       unsigned long long a,
                                       unsigned long long b) {
    asm("fma.rn.f32x2 %0, %1, %2, %0;" : "+l"(d) : "l"(a), "l"(b));
}
__device__ __forceinline__ void mul_f2(unsigned long long& d,
                                       unsigned long long a) {
    asm("mul.rn.f32x2 %0, %0, %1;" : "+l"(d) : "l"(a));
}
__device__ __forceinline__ float2 unp_f2(unsigned long long v) {
    float2 f;
    asm("mov.b64 {%0, %1}, %2;" : "=f"(f.x), "=f"(f.y) : "l"(v));
    return f;
}

// ---------------------------------------------------------------------------
// Projection: out[n,h] = X[n,:] . W[h,:] + bias[h]
// k-major smem + packed FMA. Q,K written transposed ([h][n]); V row-major.
// grid.z = which*8 + b;  which: 0=Q(A,Wq), 1=K(B,Wk), 2=V(B,Wv)
// ---------------------------------------------------------------------------
#define PJ_BK 32

__global__ __launch_bounds__(256) void proj_kernel(
    const float* __restrict__ A, const float* __restrict__ B,
    const float* __restrict__ Wq, const float* __restrict__ bq,
    const float* __restrict__ Wk, const float* __restrict__ bk,
    const float* __restrict__ Wv, const float* __restrict__ bv)
{
    __shared__ float XsT[PJ_BK][64];   // [k][n-local]
    __shared__ float WsT[PJ_BK][64];   // [k][h-local]

    const int z     = blockIdx.z;
    const int b     = z & 7;
    const int which = z >> 3;

    const float* X    = (which == 0) ? (A + (size_t)b * NA * HIDDEN)
                                     : (B + (size_t)b * NB * HIDDEN);
    const float* W    = (which == 0) ? Wq : (which == 1) ? Wk : Wv;
    const float* bias = (which == 0) ? bq : (which == 1) ? bk : bv;

    const int r0 = blockIdx.x * 64;    // n block
    const int h0 = blockIdx.y * 64;    // h block
    const int tid = threadIdx.x;
    const int tx = tid & 15;
    const int ty = tid >> 4;

    unsigned long long acc2[2][4];
    #pragma unroll
    for (int i = 0; i < 2; i++)
        #pragma unroll
        for (int j = 0; j < 4; j++) acc2[i][j] = 0ull;

    const int lr = tid & 63;     // lane-row for transpose loads (conflict-free stores)
    const int cs = tid >> 6;     // 0..3

    for (int k0 = 0; k0 < HIDDEN; k0 += PJ_BK) {
        #pragma unroll
        for (int s = 0; s < 2; s++) {
            const int kl = cs * 8 + s * 4;
            const float4 xv = *(const float4*)&X[(size_t)(r0 + lr) * HIDDEN + k0 + kl];
            XsT[kl + 0][lr] = xv.x; XsT[kl + 1][lr] = xv.y;
            XsT[kl + 2][lr] = xv.z; XsT[kl + 3][lr] = xv.w;
            const float4 wv = *(const float4*)&W[(size_t)(h0 + lr) * HIDDEN + k0 + kl];
            WsT[kl + 0][lr] = wv.x; WsT[kl + 1][lr] = wv.y;
            WsT[kl + 2][lr] = wv.z; WsT[kl + 3][lr] = wv.w;
        }
        __syncthreads();

        #pragma unroll 8
        for (int k = 0; k < PJ_BK; k++) {
            const ulonglong2 xp = *(const ulonglong2*)&XsT[k][4 * ty];
            const float4 wv = *(const float4*)&WsT[k][4 * tx];
            const unsigned long long b0 = dup_f2(wv.x), b1 = dup_f2(wv.y),
                                     b2 = dup_f2(wv.z), b3 = dup_f2(wv.w);
            fma_f2(acc2[0][0], xp.x, b0); fma_f2(acc2[0][1], xp.x, b1);
            fma_f2(acc2[0][2], xp.x, b2); fma_f2(acc2[0][3], xp.x, b3);
            fma_f2(acc2[1][0], xp.y, b0); fma_f2(acc2[1][1], xp.y, b1);
            fma_f2(acc2[1][2], xp.y, b2); fma_f2(acc2[1][3], xp.y, b3);
        }
        __syncthreads();
    }

    // Unpack: row i (= 4ty+i), col j (= 4tx+j)
    float s[4][4];
    #pragma unroll
    for (int rp = 0; rp < 2; rp++)
        #pragma unroll
        for (int j = 0; j < 4; j++) {
            const float2 p = unp_f2(acc2[rp][j]);
            s[2 * rp + 0][j] = p.x;
            s[2 * rp + 1][j] = p.y;
        }

    if (which < 2) {
        // Transposed write: out_t[h][n], float4 along n
        float* out_t = ((which == 0) ? g_Qt : g_Kt) + (size_t)b * HIDDEN * 2048;
        #pragma unroll
        for (int j = 0; j < 4; j++) {
            const int h = h0 + 4 * tx + j;
            const float bb = bias[h];
            float4 o;
            o.x = s[0][j] + bb; o.y = s[1][j] + bb;
            o.z = s[2][j] + bb; o.w = s[3][j] + bb;
            *(float4*)&out_t[(size_t)h * 2048 + r0 + 4 * ty] = o;
        }
    } else {
        // Row-major write: out[n][h]
        float* out = g_V + (size_t)b * 2048 * HIDDEN;
        const float b0 = bias[h0 + 4 * tx + 0], b1 = bias[h0 + 4 * tx + 1];
        const float b2 = bias[h0 + 4 * tx + 2], b3 = bias[h0 + 4 * tx + 3];
        #pragma unroll
        for (int i = 0; i < 4; i++) {
            float4 o;
            o.x = s[i][0] + b0; o.y = s[i][1] + b1;
            o.z = s[i][2] + b2; o.w = s[i][3] + b3;
            *(float4*)&out[(size_t)(r0 + 4 * ty + i) * HIDDEN + h0 + 4 * tx] = o;
        }
    }
}

// ---------------------------------------------------------------------------
// Fused masked attention, flash-style online softmax, fp32 with f32x2 FMA.
// BLOCK_M=64 q rows / CTA, BLOCK_N=64 kv rows / tile.
// smem: QsT[k=256][64], KsT[256][64], Vs[64][256], Ps[64][68], Msk[64]
// ---------------------------------------------------------------------------
#define FM 64
#define FN 64
#define PS_LD 68

#define ATTN_SMEM_FLOATS (HIDDEN * FM + HIDDEN * FN + FN * HIDDEN + FM * PS_LD + FN)

__global__ __launch_bounds__(256, 1) void attn_kernel(
    const int* __restrict__ maskB, float* __restrict__ out)
{
    extern __shared__ float sm[];
    float* QsT = sm;                        // [256][64]
    float* KsT = QsT + HIDDEN * FM;         // [256][64]
    float* Vs  = KsT + HIDDEN * FN;         // [64][256]
    float* Ps  = Vs + FN * HIDDEN;          // [64][68]
    float* Msk = Ps + FM * PS_LD;           // [64]

    const int b  = blockIdx.y;
    const int q0 = blockIdx.x * FM;
    const int tid = threadIdx.x;
    const int tx = tid & 15;
    const int ty = tid >> 4;

    const float* Qt = g_Qt + (size_t)b * HIDDEN * NA;
    const float* Kt = g_Kt + (size_t)b * HIDDEN * NB;
    const float* V  = g_V  + (size_t)b * NB * HIDDEN;
    const int*   mk = maskB + b * NB;

    // Load Q tile, already k-major in gmem: QsT[h][m] <- Qt[h][q0+m]
    for (int i = tid; i < HIDDEN * (FM / 4); i += 256) {
        const int h  = i >> 4;        // 0..255
        const int fc = i & 15;        // float4 col
        const float4 v = *(const float4*)&Qt[(size_t)h * 2048 + q0 + 4 * fc];
        *(float4*)&QsT[h * FM + 4 * fc] = v;
    }

    unsigned long long O2[4][8];
    #pragma unroll
    for (int i = 0; i < 4; i++)
        #pragma unroll
        for (int c = 0; c < 8; c++) O2[i][c] = 0ull;

    float mrow[4], lrow[4];
    #pragma unroll
    for (int i = 0; i < 4; i++) { mrow[i] = -1e30f; lrow[i] = 0.f; }

    const float scale = 0.0625f;  // 1/sqrt(256)

    for (int t = 0; t < NB / FN; t++) {
        const int n0 = t * FN;

        // K tile (k-major in gmem) and V tile (row-major)
        for (int i = tid; i < HIDDEN * (FN / 4); i += 256) {
            const int h  = i >> 4;
            const int fc = i & 15;
            const float4 v = *(const float4*)&Kt[(size_t)h * 2048 + n0 + 4 * fc];
            *(float4*)&KsT[h * FN + 4 * fc] = v;
        }
        for (int i = tid; i < FN * (HIDDEN / 4); i += 256) {
            const int r  = i >> 6;
            const int fc = i & 63;
            const float4 v = *(const float4*)&V[(size_t)(n0 + r) * HIDDEN + 4 * fc];
            *(float4*)&Vs[r * HIDDEN + 4 * fc] = v;
        }
        if (tid < FN) Msk[tid] = (mk[n0 + tid] == 0) ? -1e30f : 0.f;
        __syncthreads();

        // S = Q K^T : rows packed in pairs, 8 FFMA2 per k per thread
        unsigned long long sacc2[2][4];
        #pragma unroll
        for (int rp = 0; rp < 2; rp++)
            #pragma unroll
            for (int j = 0; j < 4; j++) sacc2[rp][j] = 0ull;

        #pragma unroll 8
        for (int k = 0; k < HIDDEN; k++) {
            const ulonglong2 qp = *(const ulonglong2*)&QsT[k * FM + 4 * ty];
            const float4 kv = *(const float4*)&KsT[k * FN + 4 * tx];
            const unsigned long long b0 = dup_f2(kv.x), b1 = dup_f2(kv.y),
                                     b2 = dup_f2(kv.z), b3 = dup_f2(kv.w);
            fma_f2(sacc2[0][0], qp.x, b0); fma_f2(sacc2[0][1], qp.x, b1);
            fma_f2(sacc2[0][2], qp.x, b2); fma_f2(sacc2[0][3], qp.x, b3);
            fma_f2(sacc2[1][0], qp.y, b0); fma_f2(sacc2[1][1], qp.y, b1);
            fma_f2(sacc2[1][2], qp.y, b2); fma_f2(sacc2[1][3], qp.y, b3);
        }

        // Unpack, scale + mask
        float s[4][4];
        #pragma unroll
        for (int rp = 0; rp < 2; rp++)
            #pragma unroll
            for (int j = 0; j < 4; j++) {
                const float2 p = unp_f2(sacc2[rp][j]);
                s[2 * rp + 0][j] = p.x;
                s[2 * rp + 1][j] = p.y;
            }
        #pragma unroll
        for (int i = 0; i < 4; i++)
            #pragma unroll
            for (int j = 0; j < 4; j++)
                s[i][j] = s[i][j] * scale + Msk[4 * tx + j];

        // Online softmax per row (rows split over tx half-warps)
        #pragma unroll
        for (int i = 0; i < 4; i++) {
            float tmax = fmaxf(fmaxf(s[i][0], s[i][1]), fmaxf(s[i][2], s[i][3]));
            #pragma unroll
            for (int off = 1; off < 16; off <<= 1)
                tmax = fmaxf(tmax, __shfl_xor_sync(0xffffffffu, tmax, off));

            const float mnew  = fmaxf(mrow[i], tmax);
            const float alpha = __expf(mrow[i] - mnew);
            float rsum = 0.f;
            #pragma unroll
            for (int j = 0; j < 4; j++) {
                const float p = __expf(s[i][j] - mnew);
                s[i][j] = p;
                rsum += p;
            }
            #pragma unroll
            for (int off = 1; off < 16; off <<= 1)
                rsum += __shfl_xor_sync(0xffffffffu, rsum, off);

            lrow[i] = lrow[i] * alpha + rsum;
            mrow[i] = mnew;

            const unsigned long long av = dup_f2(alpha);
            #pragma unroll
            for (int c = 0; c < 8; c++) mul_f2(O2[i][c], av);

            #pragma unroll
            for (int j = 0; j < 4; j++)
                Ps[(4 * ty + i) * PS_LD + 4 * tx + j] = s[i][j];
        }
        __syncthreads();

        // O += P @ V  (4 rows x 16 cols as 8 f32x2 pairs per row)
        #pragma unroll 4
        for (int j = 0; j < FN; j++) {
            const unsigned long long a0 = dup_f2(Ps[(4 * ty + 0) * PS_LD + j]);
            const unsigned long long a1 = dup_f2(Ps[(4 * ty + 1) * PS_LD + j]);
            const unsigned long long a2 = dup_f2(Ps[(4 * ty + 2) * PS_LD + j]);
            const unsigned long long a3 = dup_f2(Ps[(4 * ty + 3) * PS_LD + j]);
            const float* vrow = &Vs[j * HIDDEN + tx * 16];
            const ulonglong2 v0 = *(const ulonglong2*)&vrow[0];
            const ulonglong2 v1 = *(const ulonglong2*)&vrow[4];
            const ulonglong2 v2 = *(const ulonglong2*)&vrow[8];
            const ulonglong2 v3 = *(const ulonglong2*)&vrow[12];
            const unsigned long long vp[8] = {v0.x, v0.y, v1.x, v1.y,
                                              v2.x, v2.y, v3.x, v3.y};
            #pragma unroll
            for (int c = 0; c < 8; c++) {
                fma_f2(O2[0][c], a0, vp[c]);
                fma_f2(O2[1][c], a1, vp[c]);
                fma_f2(O2[2][c], a2, vp[c]);
                fma_f2(O2[3][c], a3, vp[c]);
            }
        }
        __syncthreads();
    }

    // Epilogue: divide by l, write out (cols = tx*16 + 2c + {0,1})
    #pragma unroll
    for (int i = 0; i < 4; i++) {
        const float inv = 1.f / lrow[i];
        const size_t row = (size_t)b * NA + (q0 + 4 * ty + i);
        #pragma unroll
        for (int u = 0; u < 4; u++) {
            const float2 pa = unp_f2(O2[i][2 * u + 0]);
            const float2 pb = unp_f2(O2[i][2 * u + 1]);
            float4 o;
            o.x = pa.x * inv; o.y = pa.y * inv;
            o.z = pb.x * inv; o.w = pb.y * inv;
            *(float4*)&out[row * HIDDEN + tx * 16 + 4 * u] = o;
        }
    }
}

// ---------------------------------------------------------------------------
extern "C" void kernel_launch(void* const* d_in, const int* in_sizes, int n_in,
                              void* d_out, int out_size)
{
    const float* A    = (const float*)d_in[0];
    const float* B    = (const float*)d_in[1];
    const int*   mask = (const int*)  d_in[2];
    const float* Wq   = (const float*)d_in[3];
    const float* bq   = (const float*)d_in[4];
    const float* Wk   = (const float*)d_in[5];
    const float* bk   = (const float*)d_in[6];
    const float* Wv   = (const float*)d_in[7];
    const float* bv   = (const float*)d_in[8];
    float* out = (float*)d_out;

    (void)in_sizes; (void)n_in; (void)out_size;

    static const size_t attn_smem = (size_t)ATTN_SMEM_FLOATS * sizeof(float);
    cudaFuncSetAttribute(attn_kernel, cudaFuncAttributeMaxDynamicSharedMemorySize,
                         (int)attn_smem);

    dim3 pg(NA / 64, HIDDEN / 64, 3 * BATCH);
    proj_kernel<<<pg, 256>>>(A, B, Wq, bq, Wk, bk, Wv, bv);

    dim3 ag(NA / FM, BATCH);
    attn_kernel<<<ag, 256, attn_smem>>>(mask, out);
}

// round 5
// speedup vs baseline: 3.3292x; 3.3048x over previous
#include <cuda_runtime.h>
#include <cstdint>

#define HID    256
#define BATCH  8
#define NA     2048
#define NB     2048
#define FM     64              // q rows per CTA
#define FN     32              // kv rows per tile
#define NT     (NB / FN)       // 64 tiles

// Projection outputs: Q,K row-major [b][n][h] (Q pre-scaled by 1/16, all tf32-rounded);
// V transposed [b][h][n] (tf32-rounded).
__device__ float g_Q [(size_t)BATCH * NA * HID];
__device__ float g_K [(size_t)BATCH * NB * HID];
__device__ float g_Vt[(size_t)BATCH * HID * NB];

// ---------------- f32x2 helpers (projection) ----------------
__device__ __forceinline__ unsigned long long dup_f2(float x) {
    unsigned long long r;
    asm("mov.b64 %0, {%1, %1};" : "=l"(r) : "f"(x));
    return r;
}
__device__ __forceinline__ void fma_f2(unsigned long long& d,
                                       unsigned long long a,
                                       unsigned long long b) {
    asm("fma.rn.f32x2 %0, %1, %2, %0;" : "+l"(d) : "l"(a), "l"(b));
}
__device__ __forceinline__ float2 unp_f2(unsigned long long v) {
    float2 f;
    asm("mov.b64 {%0, %1}, %2;" : "=f"(f.x), "=f"(f.y) : "l"(v));
    return f;
}
__device__ __forceinline__ float tf32r(float x) {
    uint32_t r;
    asm("cvt.rna.tf32.f32 %0, %1;" : "=r"(r) : "f"(x));
    return __uint_as_float(r);
}
__device__ __forceinline__ uint32_t tf32u(float x) {
    uint32_t r;
    asm("cvt.rna.tf32.f32 %0, %1;" : "=r"(r) : "f"(x));
    return r;
}

// ---------------- mma / ldmatrix / cp.async ----------------
__device__ __forceinline__ uint32_t smem_u32(const void* p) {
    uint32_t a;
    asm("{ .reg .u64 t; cvta.to.shared.u64 t, %1; cvt.u32.u64 %0, t; }"
        : "=r"(a) : "l"(p));
    return a;
}
__device__ __forceinline__ void ldsm4(uint32_t* r, uint32_t addr) {
    asm volatile("ldmatrix.sync.aligned.m8n8.x4.shared.b16 {%0,%1,%2,%3}, [%4];"
                 : "=r"(r[0]), "=r"(r[1]), "=r"(r[2]), "=r"(r[3]) : "r"(addr));
}
// A regs must be given in order (a0,a1,a2,a3) = (r0, r2, r1, r3) of ldmatrix out.
__device__ __forceinline__ void mma8(float* c, const uint32_t* r,
                                     uint32_t b0, uint32_t b1) {
    asm volatile(
        "mma.sync.aligned.m16n8k8.row.col.f32.tf32.tf32.f32 "
        "{%0,%1,%2,%3}, {%4,%5,%6,%7}, {%8,%9}, {%0,%1,%2,%3};"
        : "+f"(c[0]), "+f"(c[1]), "+f"(c[2]), "+f"(c[3])
        : "r"(r[0]), "r"(r[2]), "r"(r[1]), "r"(r[3]), "r"(b0), "r"(b1));
}
__device__ __forceinline__ void cp16(uint32_t saddr, const void* g) {
    asm volatile("cp.async.cg.shared.global [%0], [%1], 16;"
                 :: "r"(saddr), "l"(g) : "memory");
}
#define CP_COMMIT() asm volatile("cp.async.commit_group;" ::: "memory")
#define CP_WAIT(N)  asm volatile("cp.async.wait_group %0;" :: "n"(N) : "memory")
__device__ __forceinline__ void sts_v2(uint32_t addr, uint32_t a, uint32_t b) {
    asm volatile("st.shared.v2.b32 [%0], {%1,%2};" :: "r"(addr), "r"(a), "r"(b)
                 : "memory");
}

// ---------------- projection (R2-validated SGEMM + tf32 epilogue) ----------------
#define PJ_BK 32
__global__ __launch_bounds__(256) void proj_kernel(
    const float* __restrict__ A, const float* __restrict__ B,
    const float* __restrict__ Wq, const float* __restrict__ bq,
    const float* __restrict__ Wk, const float* __restrict__ bk,
    const float* __restrict__ Wv, const float* __restrict__ bv)
{
    __shared__ float XsT[PJ_BK][64];
    __shared__ float WsT[PJ_BK][64];

    const int z = blockIdx.z;
    const int b = z & 7;
    const int which = z >> 3;

    const float* X    = (which == 0) ? (A + (size_t)b * NA * HID)
                                     : (B + (size_t)b * NB * HID);
    const float* W    = (which == 0) ? Wq : (which == 1) ? Wk : Wv;
    const float* bias = (which == 0) ? bq : (which == 1) ? bk : bv;

    const int r0 = blockIdx.x * 64;
    const int h0 = blockIdx.y * 64;
    const int tid = threadIdx.x;
    const int tx = tid & 15;
    const int ty = tid >> 4;

    unsigned long long acc2[2][4];
    #pragma unroll
    for (int i = 0; i < 2; i++)
        #pragma unroll
        for (int j = 0; j < 4; j++) acc2[i][j] = 0ull;

    const int lr = tid & 63;
    const int cs = tid >> 6;

    for (int k0 = 0; k0 < HID; k0 += PJ_BK) {
        #pragma unroll
        for (int s = 0; s < 2; s++) {
            const int kl = cs * 8 + s * 4;
            const float4 xv = *(const float4*)&X[(size_t)(r0 + lr) * HID + k0 + kl];
            XsT[kl + 0][lr] = xv.x; XsT[kl + 1][lr] = xv.y;
            XsT[kl + 2][lr] = xv.z; XsT[kl + 3][lr] = xv.w;
            const float4 wv = *(const float4*)&W[(size_t)(h0 + lr) * HID + k0 + kl];
            WsT[kl + 0][lr] = wv.x; WsT[kl + 1][lr] = wv.y;
            WsT[kl + 2][lr] = wv.z; WsT[kl + 3][lr] = wv.w;
        }
        __syncthreads();

        #pragma unroll 8
        for (int k = 0; k < PJ_BK; k++) {
            const ulonglong2 xp = *(const ulonglong2*)&XsT[k][4 * ty];
            const float4 wv = *(const float4*)&WsT[k][4 * tx];
            const unsigned long long b0 = dup_f2(wv.x), b1 = dup_f2(wv.y),
                                     b2 = dup_f2(wv.z), b3 = dup_f2(wv.w);
            fma_f2(acc2[0][0], xp.x, b0); fma_f2(acc2[0][1], xp.x, b1);
            fma_f2(acc2[0][2], xp.x, b2); fma_f2(acc2[0][3], xp.x, b3);
            fma_f2(acc2[1][0], xp.y, b0); fma_f2(acc2[1][1], xp.y, b1);
            fma_f2(acc2[1][2], xp.y, b2); fma_f2(acc2[1][3], xp.y, b3);
        }
        __syncthreads();
    }

    float s[4][4];
    #pragma unroll
    for (int rp = 0; rp < 2; rp++)
        #pragma unroll
        for (int j = 0; j < 4; j++) {
            const float2 p = unp_f2(acc2[rp][j]);
            s[2 * rp + 0][j] = p.x;
            s[2 * rp + 1][j] = p.y;
        }

    if (which < 2) {
        float* out = ((which == 0) ? g_Q : g_K) + (size_t)b * 2048 * HID;
        const float qs = (which == 0) ? 0.0625f : 1.0f;  // fold 1/sqrt(256) into Q
        const float b0 = bias[h0 + 4 * tx + 0], b1 = bias[h0 + 4 * tx + 1];
        const float b2 = bias[h0 + 4 * tx + 2], b3 = bias[h0 + 4 * tx + 3];
        #pragma unroll
        for (int i = 0; i < 4; i++) {
            float4 o;
            o.x = tf32r((s[i][0] + b0) * qs); o.y = tf32r((s[i][1] + b1) * qs);
            o.z = tf32r((s[i][2] + b2) * qs); o.w = tf32r((s[i][3] + b3) * qs);
            *(float4*)&out[(size_t)(r0 + 4 * ty + i) * HID + h0 + 4 * tx] = o;
        }
    } else {
        float* out_t = g_Vt + (size_t)b * HID * 2048;
        #pragma unroll
        for (int j = 0; j < 4; j++) {
            const int h = h0 + 4 * tx + j;
            const float bb = bias[h];
            float4 o;
            o.x = tf32r(s[0][j] + bb); o.y = tf32r(s[1][j] + bb);
            o.z = tf32r(s[2][j] + bb); o.w = tf32r(s[3][j] + bb);
            *(float4*)&out_t[(size_t)h * 2048 + r0 + 4 * ty] = o;
        }
    }
}

// ---------------- attention smem layout (float indices) ----------------
#define QLD 260                         // 256 + 4 pad (4-bank shift per row)
#define VLD 36                          // 32 + 4 pad
#define PLD 36
#define QS_F      0                     // 64 x 260        = 16640
#define KS_F(bf)  (16640 + (bf) * 8320) // 2 x 32 x 260
#define VS_F(bf)  (33280 + (bf) * 9216) // 2 x 256 x 36
#define PS_F      51712                 // 64 x 36         = 2304
#define MK_F      54016                 // 2048 mask floats
#define LR_F      56064                 // 2 x 64 row sums
#define SMEM_FLOATS 56192
#define SMEM_BYTES  (SMEM_FLOATS * 4)   // 224768 <= 232448 opt-in max

// ---------------- tile loaders ----------------
__device__ __forceinline__ void load_Q(uint32_t smb, const float* Qb, int q0, int tid) {
    #pragma unroll
    for (int i = 0; i < 16; i++) {
        const int c  = tid + i * 256;
        const int r  = c >> 6;
        const int c4 = c & 63;
        cp16(smb + (QS_F + r * QLD + c4 * 4) * 4,
             Qb + (size_t)(q0 + r) * HID + c4 * 4);
    }
}
__device__ __forceinline__ void load_K(uint32_t smb, int bf, const float* Kb,
                                       int n0, int tid) {
    #pragma unroll
    for (int i = 0; i < 8; i++) {
        const int c  = tid + i * 256;
        const int r  = c >> 6;
        const int c4 = c & 63;
        cp16(smb + (KS_F(bf) + r * QLD + c4 * 4) * 4,
             Kb + (size_t)(n0 + r) * HID + c4 * 4);
    }
}
__device__ __forceinline__ void load_V(uint32_t smb, int bf, const float* Vtb,
                                       int n0, int tid) {
    #pragma unroll
    for (int i = 0; i < 8; i++) {
        const int c  = tid + i * 256;
        const int h  = c >> 3;
        const int c4 = c & 7;
        cp16(smb + (VS_F(bf) + h * VLD + c4 * 4) * 4,
             Vtb + (size_t)h * 2048 + n0 + c4 * 4);
    }
}

// ---------------- attention: 256 threads / 8 warps, 64 q rows per CTA ----------------
__global__ __launch_bounds__(256, 1) void attn_kernel(
    const int* __restrict__ maskB, float* __restrict__ out)
{
    extern __shared__ float sm[];
    const uint32_t smb = smem_u32(sm);

    const int tid  = threadIdx.x;
    const int lane = tid & 31;
    const int wid  = tid >> 5;
    const int mt   = wid & 3;    // m16 tile index (rows mt*16..)
    const int nh   = wid >> 2;   // n-half for S / h-half for PV
    const int g    = lane >> 2;
    const int tg   = lane & 3;
    // ldmatrix x4 lane address pattern: row offset + (0 or +4 floats)
    const int lsrow = (lane & 7) + 8 * (lane >> 4);
    const int lscol = 4 * ((lane >> 3) & 1);

    const int b  = blockIdx.y;
    const int q0 = blockIdx.x * FM;

    const float* Qb  = g_Q  + (size_t)b * NA * HID;
    const float* Kb  = g_K  + (size_t)b * NB * HID;
    const float* Vtb = g_Vt + (size_t)b * HID * NB;
    const int*   mk  = maskB + b * NB;

    // stage mask as 0/1 floats
    for (int i = tid; i < NB; i += 256) sm[MK_F + i] = (mk[i] != 0) ? 1.f : 0.f;

    load_Q(smb, Qb, q0, tid);                 CP_COMMIT();  // G0
    load_K(smb, 0, Kb, 0, tid);
    load_V(smb, 0, Vtb, 0, tid);              CP_COMMIT();  // G1 (tile 0)
    load_K(smb, 1, Kb, FN, tid);
    load_V(smb, 1, Vtb, FN, tid);             CP_COMMIT();  // G2 (tile 1)

    // lane-fixed smem byte addresses for ldmatrix
    const uint32_t aQ  = smb + (QS_F + (mt * 16 + lsrow) * QLD + lscol) * 4;
    const uint32_t bK0 = smb + (KS_F(0) + (nh * 16 + lsrow) * QLD + lscol) * 4;
    const uint32_t bK1 = smb + (KS_F(1) + (nh * 16 + lsrow) * QLD + lscol) * 4;
    const uint32_t aP  = smb + (PS_F + (mt * 16 + lsrow) * PLD + lscol) * 4;
    const uint32_t bV0 = smb + (VS_F(0) + (nh * 128 + lsrow) * VLD + lscol) * 4;
    const uint32_t bV1 = smb + (VS_F(1) + (nh * 128 + lsrow) * VLD + lscol) * 4;
    const uint32_t pw0 = smb + (PS_F + (mt * 16 + g) * PLD + nh * 16 + 2 * tg) * 4;

    float o[16][4];
    #pragma unroll
    for (int n = 0; n < 16; n++)
        #pragma unroll
        for (int j = 0; j < 4; j++) o[n][j] = 0.f;
    float lg = 0.f, lg8 = 0.f;

    for (int t = 0; t < NT; t++) {
        CP_WAIT(1);
        __syncthreads();

        // ---- S = Q K^T (scaled already): warp computes m16 x n16 ----
        const uint32_t bK = (t & 1) ? bK1 : bK0;
        float c[2][4] = {{0.f, 0.f, 0.f, 0.f}, {0.f, 0.f, 0.f, 0.f}};
        #pragma unroll
        for (int ks = 0; ks < 32; ks++) {
            uint32_t a[4], bb[4];
            ldsm4(a, aQ + ks * 32);
            ldsm4(bb, bK + ks * 32);
            mma8(c[0], a, bb[0], bb[1]);
            mma8(c[1], a, bb[2], bb[3]);
        }

        // ---- softmax numerator (no-max trick) + P to smem ----
        const int n0 = t * FN;
        #pragma unroll
        for (int nb = 0; nb < 2; nb++) {
            const float mv0 = sm[MK_F + n0 + nh * 16 + nb * 8 + 2 * tg + 0];
            const float mv1 = sm[MK_F + n0 + nh * 16 + nb * 8 + 2 * tg + 1];
            const float e00 = __expf(c[nb][0]) * mv0;
            const float e01 = __expf(c[nb][1]) * mv1;
            const float e10 = __expf(c[nb][2]) * mv0;
            const float e11 = __expf(c[nb][3]) * mv1;
            lg  += e00 + e01;
            lg8 += e10 + e11;
            sts_v2(pw0 + nb * 32, tf32u(e00), tf32u(e01));
            sts_v2(pw0 + nb * 32 + 8 * PLD * 4, tf32u(e10), tf32u(e11));
        }
        __syncthreads();

        // ---- O += P V : warp computes m16 x n128 (its h-half) ----
        const uint32_t bV = (t & 1) ? bV1 : bV0;
        #pragma unroll
        for (int ks = 0; ks < 4; ks++) {
            uint32_t a[4];
            ldsm4(a, aP + ks * 32);
            #pragma unroll
            for (int pr = 0; pr < 8; pr++) {
                uint32_t bb[4];
                ldsm4(bb, bV + pr * (16 * VLD * 4) + ks * 32);
                mma8(o[2 * pr + 0], a, bb[0], bb[1]);
                mma8(o[2 * pr + 1], a, bb[2], bb[3]);
            }
        }
        __syncthreads();

        if (t + 2 < NT) {
            load_K(smb, t & 1, Kb, (t + 2) * FN, tid);
            load_V(smb, t & 1, Vtb, (t + 2) * FN, tid);
        }
        CP_COMMIT();
    }

    // ---- l reduction: quad shuffle, then cross-n-half via smem ----
    lg  += __shfl_xor_sync(0xffffffffu, lg, 1);
    lg  += __shfl_xor_sync(0xffffffffu, lg, 2);
    lg8 += __shfl_xor_sync(0xffffffffu, lg8, 1);
    lg8 += __shfl_xor_sync(0xffffffffu, lg8, 2);
    if (tg == 0) {
        sm[LR_F + nh * 64 + mt * 16 + g]     = lg;
        sm[LR_F + nh * 64 + mt * 16 + g + 8] = lg8;
    }
    __syncthreads();

    const int r0  = mt * 16 + g;
    const float inv0 = 1.f / (sm[LR_F + r0]     + sm[LR_F + 64 + r0]);
    const float inv8 = 1.f / (sm[LR_F + r0 + 8] + sm[LR_F + 64 + r0 + 8]);

    float* outb = out + ((size_t)b * NA + q0) * HID;
    #pragma unroll
    for (int nb = 0; nb < 16; nb++) {
        const int col = nh * 128 + nb * 8 + 2 * tg;
        float2 v0, v8;
        v0.x = o[nb][0] * inv0; v0.y = o[nb][1] * inv0;
        v8.x = o[nb][2] * inv8; v8.y = o[nb][3] * inv8;
        *(float2*)&outb[(size_t)(r0)     * HID + col] = v0;
        *(float2*)&outb[(size_t)(r0 + 8) * HID + col] = v8;
    }
}

// ---------------------------------------------------------------------------
extern "C" void kernel_launch(void* const* d_in, const int* in_sizes, int n_in,
                              void* d_out, int out_size)
{
    const float* A    = (const float*)d_in[0];
    const float* B    = (const float*)d_in[1];
    const int*   mask = (const int*)  d_in[2];
    const float* Wq   = (const float*)d_in[3];
    const float* bq   = (const float*)d_in[4];
    const float* Wk   = (const float*)d_in[5];
    const float* bk   = (const float*)d_in[6];
    const float* Wv   = (const float*)d_in[7];
    const float* bv   = (const float*)d_in[8];
    float* out = (float*)d_out;

    (void)in_sizes; (void)n_in; (void)out_size;

    cudaFuncSetAttribute(attn_kernel, cudaFuncAttributeMaxDynamicSharedMemorySize,
                         SMEM_BYTES);

    dim3 pg(NA / 64, HID / 64, 3 * BATCH);
    proj_kernel<<<pg, 256>>>(A, B, Wq, bq, Wk, bk, Wv, bv);

    dim3 ag(NA / FM, BATCH);
    attn_kernel<<<ag, 256, SMEM_BYTES>>>(mask, out);
}

// round 6
// speedup vs baseline: 5.1145x; 1.5363x over previous
#include <cuda_runtime.h>
#include <cstdint>

#define HID    256
#define BATCH  8
#define NA     2048
#define NB     2048
#define FM     64
#define FN     64
#define NT     (NB / FN)       // 32 tiles

// tf32-rounded copies of inputs (round_kernel output, proj input)
__device__ float g_Ar[(size_t)BATCH * NA * HID];
__device__ float g_Br[(size_t)BATCH * NB * HID];
__device__ float g_Wr[3 * HID * HID];
// Projection outputs: Q,K row-major (Q pre-scaled 1/16), V transposed; all tf32-rounded.
__device__ float g_Q [(size_t)BATCH * NA * HID];
__device__ float g_K [(size_t)BATCH * NB * HID];
__device__ float g_Vt[(size_t)BATCH * HID * NB];

// ---------------- helpers ----------------
__device__ __forceinline__ float tf32r(float x) {
    uint32_t r;
    asm("cvt.rna.tf32.f32 %0, %1;" : "=r"(r) : "f"(x));
    return __uint_as_float(r);
}
__device__ __forceinline__ uint32_t tf32u(float x) {
    uint32_t r;
    asm("cvt.rna.tf32.f32 %0, %1;" : "=r"(r) : "f"(x));
    return r;
}
__device__ __forceinline__ uint32_t smem_u32(const void* p) {
    uint32_t a;
    asm("{ .reg .u64 t; cvta.to.shared.u64 t, %1; cvt.u32.u64 %0, t; }"
        : "=r"(a) : "l"(p));
    return a;
}
__device__ __forceinline__ void ldsm4(uint32_t* r, uint32_t addr) {
    asm volatile("ldmatrix.sync.aligned.m8n8.x4.shared.b16 {%0,%1,%2,%3}, [%4];"
                 : "=r"(r[0]), "=r"(r[1]), "=r"(r[2]), "=r"(r[3]) : "r"(addr));
}
// A regs in order (r0, r2, r1, r3) of ldmatrix output (validated R5).
__device__ __forceinline__ void mma8(float* c, const uint32_t* r,
                                     uint32_t b0, uint32_t b1) {
    asm volatile(
        "mma.sync.aligned.m16n8k8.row.col.f32.tf32.tf32.f32 "
        "{%0,%1,%2,%3}, {%4,%5,%6,%7}, {%8,%9}, {%0,%1,%2,%3};"
        : "+f"(c[0]), "+f"(c[1]), "+f"(c[2]), "+f"(c[3])
        : "r"(r[0]), "r"(r[2]), "r"(r[1]), "r"(r[3]), "r"(b0), "r"(b1));
}
__device__ __forceinline__ void cp16(uint32_t saddr, const void* g) {
    asm volatile("cp.async.cg.shared.global [%0], [%1], 16;"
                 :: "r"(saddr), "l"(g) : "memory");
}
#define CP_COMMIT() asm volatile("cp.async.commit_group;" ::: "memory")
#define CP_WAIT(N)  asm volatile("cp.async.wait_group %0;" :: "n"(N) : "memory")
__device__ __forceinline__ void sts_v2(uint32_t addr, uint32_t a, uint32_t b) {
    asm volatile("st.shared.v2.b32 [%0], {%1,%2};" :: "r"(addr), "r"(a), "r"(b)
                 : "memory");
}

// ---------------- round_kernel: rna-round A, B, W into scratch ----------------
#define N_AB4 ((BATCH * NA * HID) / 4)       // 1048576 float4 each
#define N_W4  ((HID * HID) / 4)              // 16384 per W
#define N_TOT4 (2 * N_AB4 + 3 * N_W4)

__global__ __launch_bounds__(256) void round_kernel(
    const float* __restrict__ A, const float* __restrict__ B,
    const float* __restrict__ Wq, const float* __restrict__ Wk,
    const float* __restrict__ Wv)
{
    for (int i = blockIdx.x * 256 + threadIdx.x; i < N_TOT4;
         i += gridDim.x * 256) {
        const float4* src;
        float4* dst;
        if (i < N_AB4) {
            src = (const float4*)A + i;            dst = (float4*)g_Ar + i;
        } else if (i < 2 * N_AB4) {
            src = (const float4*)B + (i - N_AB4);  dst = (float4*)g_Br + (i - N_AB4);
        } else {
            int j = i - 2 * N_AB4;
            if (j < N_W4)          { src = (const float4*)Wq + j;
                                     dst = (float4*)g_Wr + j; }
            else if (j < 2 * N_W4) { src = (const float4*)Wk + (j - N_W4);
                                     dst = (float4*)(g_Wr + HID * HID) + (j - N_W4); }
            else                   { src = (const float4*)Wv + (j - 2 * N_W4);
                                     dst = (float4*)(g_Wr + 2 * HID * HID) + (j - 2 * N_W4); }
        }
        float4 v = *src;
        v.x = tf32r(v.x); v.y = tf32r(v.y); v.z = tf32r(v.z); v.w = tf32r(v.w);
        *dst = v;
    }
}

// ---------------- proj: tf32 mma GEMM, C[n,h] = X.Wt + bias ----------------
// CTA tile M=128 x N=64, k-chunks of 32, cp.async double buffer.
#define PXLD 36
#define PJ_XS(buf) ((buf) * 4608)          // 128 x 36
#define PJ_WS(buf) (9216 + (buf) * 2304)   // 64 x 36
#define PJ_CLD 68                          // C staging 128 x 68 (overlaps Xs/Ws)
#define PJ_SMEM_BYTES (13824 * 4)          // 55296

__global__ __launch_bounds__(256, 2) void proj_kernel(
    const float* __restrict__ bq, const float* __restrict__ bk,
    const float* __restrict__ bv)
{
    extern __shared__ float sm[];
    const uint32_t smb = smem_u32(sm);

    const int z = blockIdx.z;
    const int b = z & 7;
    const int which = z >> 3;

    const float* X = ((which == 0) ? g_Ar : g_Br) + (size_t)b * NA * HID;
    const float* W = g_Wr + which * HID * HID;
    const float* bias = (which == 0) ? bq : (which == 1) ? bk : bv;

    const int m0 = blockIdx.x * 128;
    const int h0 = blockIdx.y * 64;

    const int tid  = threadIdx.x;
    const int lane = tid & 31;
    const int wid  = tid >> 5;
    const int mw   = wid & 3;     // m-tile of 32 rows
    const int nh   = wid >> 2;    // n-half of 32 cols
    const int g    = lane >> 2;
    const int tg   = lane & 3;
    const int lsrow = (lane & 7) + 8 * (lane >> 4);
    const int lscol = 4 * ((lane >> 3) & 1);

    float c[8][4];
    #pragma unroll
    for (int i = 0; i < 8; i++)
        #pragma unroll
        for (int j = 0; j < 4; j++) c[i][j] = 0.f;

    // chunk loaders
    auto load_chunk = [&](int kc, int buf) {
        const int k0 = kc * 32;
        #pragma unroll
        for (int i = 0; i < 4; i++) {            // X: 128x32
            const int cc = tid + i * 256;
            const int r = cc >> 3, c4 = cc & 7;
            cp16(smb + (PJ_XS(buf) + r * PXLD + c4 * 4) * 4,
                 X + (size_t)(m0 + r) * HID + k0 + c4 * 4);
        }
        #pragma unroll
        for (int i = 0; i < 2; i++) {            // W: 64x32
            const int cc = tid + i * 256;
            const int r = cc >> 3, c4 = cc & 7;
            cp16(smb + (PJ_WS(buf) + r * PXLD + c4 * 4) * 4,
                 W + (size_t)(h0 + r) * HID + k0 + c4 * 4);
        }
    };

    load_chunk(0, 0); CP_COMMIT();

    for (int kc = 0; kc < 8; kc++) {
        if (kc < 7) load_chunk(kc + 1, (kc + 1) & 1);
        CP_COMMIT();
        CP_WAIT(1);
        __syncthreads();

        const int buf = kc & 1;
        const uint32_t aX = smb + (PJ_XS(buf) + (mw * 32 + lsrow) * PXLD + lscol) * 4;
        const uint32_t bW = smb + (PJ_WS(buf) + (nh * 32 + lsrow) * PXLD + lscol) * 4;

        #pragma unroll
        for (int ks = 0; ks < 4; ks++) {
            uint32_t a0[4], a1[4], b0[4], b1[4];
            ldsm4(a0, aX + ks * 32);
            ldsm4(a1, aX + 16 * PXLD * 4 + ks * 32);
            ldsm4(b0, bW + ks * 32);
            ldsm4(b1, bW + 16 * PXLD * 4 + ks * 32);
            mma8(c[0], a0, b0[0], b0[1]);  mma8(c[1], a0, b0[2], b0[3]);
            mma8(c[2], a0, b1[0], b1[1]);  mma8(c[3], a0, b1[2], b1[3]);
            mma8(c[4], a1, b0[0], b0[1]);  mma8(c[5], a1, b0[2], b0[3]);
            mma8(c[6], a1, b1[0], b1[1]);  mma8(c[7], a1, b1[2], b1[3]);
        }
        __syncthreads();
    }

    // stage C to smem (overlaps X/W buffers; safe after final sync)
    #pragma unroll
    for (int ms = 0; ms < 2; ms++)
        #pragma unroll
        for (int nb = 0; nb < 4; nb++) {
            const int row = mw * 32 + ms * 16 + g;
            const int col = nh * 32 + nb * 8 + 2 * tg;
            sts_v2(smb + (row * PJ_CLD + col) * 4,
                   __float_as_uint(c[ms * 4 + nb][0]),
                   __float_as_uint(c[ms * 4 + nb][1]));
            sts_v2(smb + ((row + 8) * PJ_CLD + col) * 4,
                   __float_as_uint(c[ms * 4 + nb][2]),
                   __float_as_uint(c[ms * 4 + nb][3]));
        }
    __syncthreads();

    if (which < 2) {
        float* out = ((which == 0) ? g_Q : g_K) + (size_t)b * NA * HID;
        const float qs = (which == 0) ? 0.0625f : 1.0f;
        #pragma unroll
        for (int i = 0; i < 8; i++) {
            const int cc = tid + i * 256;
            const int r = cc >> 4, c4 = cc & 15;
            const float* s = &sm[r * PJ_CLD + c4 * 4];
            const int h = h0 + c4 * 4;
            float4 o;
            o.x = tf32r((s[0] + bias[h + 0]) * qs);
            o.y = tf32r((s[1] + bias[h + 1]) * qs);
            o.z = tf32r((s[2] + bias[h + 2]) * qs);
            o.w = tf32r((s[3] + bias[h + 3]) * qs);
            *(float4*)&out[(size_t)(m0 + r) * HID + h] = o;
        }
    } else {
        float* out_t = g_Vt + (size_t)b * HID * NB;
        #pragma unroll
        for (int hh = 0; hh < 8; hh++) {
            const int h = wid * 8 + hh;
            const float bb = bias[h0 + h];
            float4 o;
            o.x = tf32r(sm[(lane * 4 + 0) * PJ_CLD + h] + bb);
            o.y = tf32r(sm[(lane * 4 + 1) * PJ_CLD + h] + bb);
            o.z = tf32r(sm[(lane * 4 + 2) * PJ_CLD + h] + bb);
            o.w = tf32r(sm[(lane * 4 + 3) * PJ_CLD + h] + bb);
            *(float4*)&out_t[(size_t)(h0 + h) * NB + m0 + lane * 4] = o;
        }
    }
}

// ---------------- attention smem layout (float indices) ----------------
#define QLD 260
#define KLD 260
#define VLD 68
#define PLD 68
#define QS_F 0                        // 64 x 260 = 16640
#define KS_F 16640                    // 64 x 260 = 16640
#define VS_F 33280                    // 256 x 68 = 17408
#define PS_F 50688                    // 64 x 68  = 4352
#define MK_F 55040                    // 2048
#define LR_F 57088                    // 128
#define SMEM_FLOATS 57216
#define SMEM_BYTES  (SMEM_FLOATS * 4) // 228864 <= 232448

__device__ __forceinline__ void load_Qt(uint32_t smb, const float* Qb, int q0, int tid) {
    #pragma unroll
    for (int i = 0; i < 16; i++) {
        const int cc = tid + i * 256;
        const int r = cc >> 6, c4 = cc & 63;
        cp16(smb + (QS_F + r * QLD + c4 * 4) * 4,
             Qb + (size_t)(q0 + r) * HID + c4 * 4);
    }
}
__device__ __forceinline__ void load_Kt(uint32_t smb, const float* Kb, int n0, int tid) {
    #pragma unroll
    for (int i = 0; i < 16; i++) {
        const int cc = tid + i * 256;
        const int r = cc >> 6, c4 = cc & 63;
        cp16(smb + (KS_F + r * KLD + c4 * 4) * 4,
             Kb + (size_t)(n0 + r) * HID + c4 * 4);
    }
}
__device__ __forceinline__ void load_Vt(uint32_t smb, const float* Vtb, int n0, int tid) {
    #pragma unroll
    for (int i = 0; i < 16; i++) {
        const int cc = tid + i * 256;
        const int h = cc >> 4, c4 = cc & 15;
        cp16(smb + (VS_F + h * VLD + c4 * 4) * 4,
             Vtb + (size_t)h * NB + n0 + c4 * 4);
    }
}

// ---------------- attention: 256 threads / 8 warps, 64 q rows / CTA ----------------
__global__ __launch_bounds__(256, 1) void attn_kernel(
    const int* __restrict__ maskB, float* __restrict__ out)
{
    extern __shared__ float sm[];
    const uint32_t smb = smem_u32(sm);

    const int tid  = threadIdx.x;
    const int lane = tid & 31;
    const int wid  = tid >> 5;
    const int mt   = wid & 3;    // m16 tile
    const int nh   = wid >> 2;   // n-half(32) for S / h-half(128) for PV
    const int g    = lane >> 2;
    const int tg   = lane & 3;
    const int lsrow = (lane & 7) + 8 * (lane >> 4);
    const int lscol = 4 * ((lane >> 3) & 1);

    const int b  = blockIdx.y;
    const int q0 = blockIdx.x * FM;

    const float* Qb  = g_Q  + (size_t)b * NA * HID;
    const float* Kb  = g_K  + (size_t)b * NB * HID;
    const float* Vtb = g_Vt + (size_t)b * HID * NB;
    const int*   mk  = maskB + b * NB;

    for (int i = tid; i < NB; i += 256) sm[MK_F + i] = (mk[i] != 0) ? 1.f : 0.f;

    // prologue: [Q + K0] group, then [V0] group -> pending [K0-grp, V0-grp]
    load_Qt(smb, Qb, q0, tid);
    load_Kt(smb, Kb, 0, tid);              CP_COMMIT();
    load_Vt(smb, Vtb, 0, tid);             CP_COMMIT();

    const uint32_t aQ  = smb + (QS_F + (mt * 16 + lsrow) * QLD + lscol) * 4;
    const uint32_t bK  = smb + (KS_F + (nh * 32 + lsrow) * KLD + lscol) * 4;
    const uint32_t aP  = smb + (PS_F + (mt * 16 + lsrow) * PLD + lscol) * 4;
    const uint32_t bV  = smb + (VS_F + (nh * 128 + lsrow) * VLD + lscol) * 4;
    const uint32_t pw0 = smb + (PS_F + (mt * 16 + g) * PLD + nh * 32 + 2 * tg) * 4;

    float o[16][4];
    #pragma unroll
    for (int n = 0; n < 16; n++)
        #pragma unroll
        for (int j = 0; j < 4; j++) o[n][j] = 0.f;
    float lg = 0.f, lg8 = 0.f;

    for (int t = 0; t < NT; t++) {
        CP_WAIT(1);                 // K_t (and Q at t=0) resident
        __syncthreads();

        // ---- S = Q K_t^T : warp m16 x n32 ----
        float c[4][4];
        #pragma unroll
        for (int i = 0; i < 4; i++)
            #pragma unroll
            for (int j = 0; j < 4; j++) c[i][j] = 0.f;
        #pragma unroll
        for (int ks = 0; ks < 32; ks++) {
            uint32_t a[4], b0[4], b1[4];
            ldsm4(a, aQ + ks * 32);
            ldsm4(b0, bK + ks * 32);
            ldsm4(b1, bK + 16 * KLD * 4 + ks * 32);
            mma8(c[0], a, b0[0], b0[1]);
            mma8(c[1], a, b0[2], b0[3]);
            mma8(c[2], a, b1[0], b1[1]);
            mma8(c[3], a, b1[2], b1[3]);
        }

        // ---- exp (no-max) + masked, P -> smem ----
        const int n0 = t * FN;
        #pragma unroll
        for (int nb = 0; nb < 4; nb++) {
            const int col = n0 + nh * 32 + nb * 8 + 2 * tg;
            const float mv0 = sm[MK_F + col], mv1 = sm[MK_F + col + 1];
            const float e00 = __expf(c[nb][0]) * mv0;
            const float e01 = __expf(c[nb][1]) * mv1;
            const float e10 = __expf(c[nb][2]) * mv0;
            const float e11 = __expf(c[nb][3]) * mv1;
            lg  += e00 + e01;
            lg8 += e10 + e11;
            sts_v2(pw0 + nb * 32, tf32u(e00), tf32u(e01));
            sts_v2(pw0 + nb * 32 + 8 * PLD * 4, tf32u(e10), tf32u(e11));
        }
        __syncthreads();            // all S-reads of K done + P visible

        if (t + 1 < NT) load_Kt(smb, Kb, (t + 1) * FN, tid);
        CP_COMMIT();                // pending: [V_t, K_{t+1}]
        CP_WAIT(1);                 // V_t resident
        __syncthreads();

        // ---- O += P V_t : warp m16 x n128 ----
        #pragma unroll
        for (int ks = 0; ks < 8; ks++) {
            uint32_t a[4];
            ldsm4(a, aP + ks * 32);
            #pragma unroll
            for (int pr = 0; pr < 8; pr++) {
                uint32_t bb[4];
                ldsm4(bb, bV + pr * (16 * VLD * 4) + ks * 32);
                mma8(o[2 * pr + 0], a, bb[0], bb[1]);
                mma8(o[2 * pr + 1], a, bb[2], bb[3]);
            }
        }
        __syncthreads();            // all PV-reads of V done

        if (t + 1 < NT) load_Vt(smb, Vtb, (t + 1) * FN, tid);
        CP_COMMIT();                // pending: [K_{t+1}, V_{t+1}]
    }

    // ---- l reduction: quad shuffle then cross-half via smem ----
    lg  += __shfl_xor_sync(0xffffffffu, lg, 1);
    lg  += __shfl_xor_sync(0xffffffffu, lg, 2);
    lg8 += __shfl_xor_sync(0xffffffffu, lg8, 1);
    lg8 += __shfl_xor_sync(0xffffffffu, lg8, 2);
    if (tg == 0) {
        sm[LR_F + nh * 64 + mt * 16 + g]     = lg;
        sm[LR_F + nh * 64 + mt * 16 + g + 8] = lg8;
    }
    __syncthreads();

    const int r0 = mt * 16 + g;
    const float inv0 = 1.f / (sm[LR_F + r0]     + sm[LR_F + 64 + r0]);
    const float inv8 = 1.f / (sm[LR_F + r0 + 8] + sm[LR_F + 64 + r0 + 8]);

    float* outb = out + ((size_t)b * NA + q0) * HID;
    #pragma unroll
    for (int nb = 0; nb < 16; nb++) {
        const int col = nh * 128 + nb * 8 + 2 * tg;
        float2 v0, v8;
        v0.x = o[nb][0] * inv0; v0.y = o[nb][1] * inv0;
        v8.x = o[nb][2] * inv8; v8.y = o[nb][3] * inv8;
        *(float2*)&outb[(size_t)(r0)     * HID + col] = v0;
        *(float2*)&outb[(size_t)(r0 + 8) * HID + col] = v8;
    }
}

// ---------------------------------------------------------------------------
extern "C" void kernel_launch(void* const* d_in, const int* in_sizes, int n_in,
                              void* d_out, int out_size)
{
    const float* A    = (const float*)d_in[0];
    const float* B    = (const float*)d_in[1];
    const int*   mask = (const int*)  d_in[2];
    const float* bq   = (const float*)d_in[4];
    const float* Wq   = (const float*)d_in[3];
    const float* Wk   = (const float*)d_in[5];
    const float* bk   = (const float*)d_in[6];
    const float* Wv   = (const float*)d_in[7];
    const float* bv   = (const float*)d_in[8];
    float* out = (float*)d_out;

    (void)in_sizes; (void)n_in; (void)out_size;

    cudaFuncSetAttribute(proj_kernel, cudaFuncAttributeMaxDynamicSharedMemorySize,
                         PJ_SMEM_BYTES);
    cudaFuncSetAttribute(attn_kernel, cudaFuncAttributeMaxDynamicSharedMemorySize,
                         SMEM_BYTES);

    round_kernel<<<1024, 256>>>(A, B, Wq, Wk, Wv);

    dim3 pg(NA / 128, HID / 64, 3 * BATCH);
    proj_kernel<<<pg, 256, PJ_SMEM_BYTES>>>(bq, bk, bv);

    dim3 ag(NA / FM, BATCH);
    attn_kernel<<<ag, 256, SMEM_BYTES>>>(mask, out);
}

// round 7
// speedup vs baseline: 5.2760x; 1.0316x over previous
#include <cuda_runtime.h>
#include <cstdint>

#define HID    256
#define BATCH  8
#define NA     2048
#define NB     2048
#define FM     128
#define FN     32
#define NT     (NB / FN)       // 64 tiles

// tf32-rounded copies of inputs (round_kernel output, proj input)
__device__ float g_Ar[(size_t)BATCH * NA * HID];
__device__ float g_Br[(size_t)BATCH * NB * HID];
__device__ float g_Wr[3 * HID * HID];
// Projection outputs: Q,K row-major (Q pre-scaled 1/16), V transposed; all tf32-rounded.
__device__ float g_Q [(size_t)BATCH * NA * HID];
__device__ float g_K [(size_t)BATCH * NB * HID];
__device__ float g_Vt[(size_t)BATCH * HID * NB];

// ---------------- helpers ----------------
__device__ __forceinline__ float tf32r(float x) {
    uint32_t r;
    asm("cvt.rna.tf32.f32 %0, %1;" : "=r"(r) : "f"(x));
    return __uint_as_float(r);
}
__device__ __forceinline__ uint32_t tf32u(float x) {
    uint32_t r;
    asm("cvt.rna.tf32.f32 %0, %1;" : "=r"(r) : "f"(x));
    return r;
}
__device__ __forceinline__ uint32_t smem_u32(const void* p) {
    uint32_t a;
    asm("{ .reg .u64 t; cvta.to.shared.u64 t, %1; cvt.u32.u64 %0, t; }"
        : "=r"(a) : "l"(p));
    return a;
}
__device__ __forceinline__ void ldsm4(uint32_t* r, uint32_t addr) {
    asm volatile("ldmatrix.sync.aligned.m8n8.x4.shared.b16 {%0,%1,%2,%3}, [%4];"
                 : "=r"(r[0]), "=r"(r[1]), "=r"(r[2]), "=r"(r[3]) : "r"(addr));
}
// A regs in order (r0, r2, r1, r3) of ldmatrix output (validated R5/R6).
__device__ __forceinline__ void mma8(float* c, const uint32_t* r,
                                     uint32_t b0, uint32_t b1) {
    asm volatile(
        "mma.sync.aligned.m16n8k8.row.col.f32.tf32.tf32.f32 "
        "{%0,%1,%2,%3}, {%4,%5,%6,%7}, {%8,%9}, {%0,%1,%2,%3};"
        : "+f"(c[0]), "+f"(c[1]), "+f"(c[2]), "+f"(c[3])
        : "r"(r[0]), "r"(r[2]), "r"(r[1]), "r"(r[3]), "r"(b0), "r"(b1));
}
__device__ __forceinline__ void cp16(uint32_t saddr, const void* g) {
    asm volatile("cp.async.cg.shared.global [%0], [%1], 16;"
                 :: "r"(saddr), "l"(g) : "memory");
}
#define CP_COMMIT() asm volatile("cp.async.commit_group;" ::: "memory")
#define CP_WAIT(N)  asm volatile("cp.async.wait_group %0;" :: "n"(N) : "memory")
__device__ __forceinline__ void sts_v2(uint32_t addr, uint32_t a, uint32_t b) {
    asm volatile("st.shared.v2.b32 [%0], {%1,%2};" :: "r"(addr), "r"(a), "r"(b)
                 : "memory");
}

// ---------------- round_kernel: rna-round A, B, W into scratch ----------------
#define N_AB4 ((BATCH * NA * HID) / 4)
#define N_W4  ((HID * HID) / 4)
#define N_TOT4 (2 * N_AB4 + 3 * N_W4)

__global__ __launch_bounds__(256) void round_kernel(
    const float* __restrict__ A, const float* __restrict__ B,
    const float* __restrict__ Wq, const float* __restrict__ Wk,
    const float* __restrict__ Wv)
{
    for (int i = blockIdx.x * 256 + threadIdx.x; i < N_TOT4;
         i += gridDim.x * 256) {
        const float4* src;
        float4* dst;
        if (i < N_AB4) {
            src = (const float4*)A + i;            dst = (float4*)g_Ar + i;
        } else if (i < 2 * N_AB4) {
            src = (const float4*)B + (i - N_AB4);  dst = (float4*)g_Br + (i - N_AB4);
        } else {
            int j = i - 2 * N_AB4;
            if (j < N_W4)          { src = (const float4*)Wq + j;
                                     dst = (float4*)g_Wr + j; }
            else if (j < 2 * N_W4) { src = (const float4*)Wk + (j - N_W4);
                                     dst = (float4*)(g_Wr + HID * HID) + (j - N_W4); }
            else                   { src = (const float4*)Wv + (j - 2 * N_W4);
                                     dst = (float4*)(g_Wr + 2 * HID * HID) + (j - 2 * N_W4); }
        }
        float4 v = *src;
        v.x = tf32r(v.x); v.y = tf32r(v.y); v.z = tf32r(v.z); v.w = tf32r(v.w);
        *dst = v;
    }
}

// ---------------- proj: tf32 mma GEMM (unchanged from R6) ----------------
#define PXLD 36
#define PJ_XS(buf) ((buf) * 4608)
#define PJ_WS(buf) (9216 + (buf) * 2304)
#define PJ_CLD 68
#define PJ_SMEM_BYTES (13824 * 4)

__global__ __launch_bounds__(256, 2) void proj_kernel(
    const float* __restrict__ bq, const float* __restrict__ bk,
    const float* __restrict__ bv)
{
    extern __shared__ float sm[];
    const uint32_t smb = smem_u32(sm);

    const int z = blockIdx.z;
    const int b = z & 7;
    const int which = z >> 3;

    const float* X = ((which == 0) ? g_Ar : g_Br) + (size_t)b * NA * HID;
    const float* W = g_Wr + which * HID * HID;
    const float* bias = (which == 0) ? bq : (which == 1) ? bk : bv;

    const int m0 = blockIdx.x * 128;
    const int h0 = blockIdx.y * 64;

    const int tid  = threadIdx.x;
    const int lane = tid & 31;
    const int wid  = tid >> 5;
    const int mw   = wid & 3;
    const int nh   = wid >> 2;
    const int g    = lane >> 2;
    const int tg   = lane & 3;
    const int lsrow = (lane & 7) + 8 * (lane >> 4);
    const int lscol = 4 * ((lane >> 3) & 1);

    float c[8][4];
    #pragma unroll
    for (int i = 0; i < 8; i++)
        #pragma unroll
        for (int j = 0; j < 4; j++) c[i][j] = 0.f;

    auto load_chunk = [&](int kc, int buf) {
        const int k0 = kc * 32;
        #pragma unroll
        for (int i = 0; i < 4; i++) {
            const int cc = tid + i * 256;
            const int r = cc >> 3, c4 = cc & 7;
            cp16(smb + (PJ_XS(buf) + r * PXLD + c4 * 4) * 4,
                 X + (size_t)(m0 + r) * HID + k0 + c4 * 4);
        }
        #pragma unroll
        for (int i = 0; i < 2; i++) {
            const int cc = tid + i * 256;
            const int r = cc >> 3, c4 = cc & 7;
            cp16(smb + (PJ_WS(buf) + r * PXLD + c4 * 4) * 4,
                 W + (size_t)(h0 + r) * HID + k0 + c4 * 4);
        }
    };

    load_chunk(0, 0); CP_COMMIT();

    for (int kc = 0; kc < 8; kc++) {
        if (kc < 7) load_chunk(kc + 1, (kc + 1) & 1);
        CP_COMMIT();
        CP_WAIT(1);
        __syncthreads();

        const int buf = kc & 1;
        const uint32_t aX = smb + (PJ_XS(buf) + (mw * 32 + lsrow) * PXLD + lscol) * 4;
        const uint32_t bW = smb + (PJ_WS(buf) + (nh * 32 + lsrow) * PXLD + lscol) * 4;

        #pragma unroll
        for (int ks = 0; ks < 4; ks++) {
            uint32_t a0[4], a1[4], b0[4], b1[4];
            ldsm4(a0, aX + ks * 32);
            ldsm4(a1, aX + 16 * PXLD * 4 + ks * 32);
            ldsm4(b0, bW + ks * 32);
            ldsm4(b1, bW + 16 * PXLD * 4 + ks * 32);
            mma8(c[0], a0, b0[0], b0[1]);  mma8(c[1], a0, b0[2], b0[3]);
            mma8(c[2], a0, b1[0], b1[1]);  mma8(c[3], a0, b1[2], b1[3]);
            mma8(c[4], a1, b0[0], b0[1]);  mma8(c[5], a1, b0[2], b0[3]);
            mma8(c[6], a1, b1[0], b1[1]);  mma8(c[7], a1, b1[2], b1[3]);
        }
        __syncthreads();
    }

    #pragma unroll
    for (int ms = 0; ms < 2; ms++)
        #pragma unroll
        for (int nb = 0; nb < 4; nb++) {
            const int row = mw * 32 + ms * 16 + g;
            const int col = nh * 32 + nb * 8 + 2 * tg;
            sts_v2(smb + (row * PJ_CLD + col) * 4,
                   __float_as_uint(c[ms * 4 + nb][0]),
                   __float_as_uint(c[ms * 4 + nb][1]));
            sts_v2(smb + ((row + 8) * PJ_CLD + col) * 4,
                   __float_as_uint(c[ms * 4 + nb][2]),
                   __float_as_uint(c[ms * 4 + nb][3]));
        }
    __syncthreads();

    if (which < 2) {
        float* out = ((which == 0) ? g_Q : g_K) + (size_t)b * NA * HID;
        const float qs = (which == 0) ? 0.0625f : 1.0f;
        #pragma unroll
        for (int i = 0; i < 8; i++) {
            const int cc = tid + i * 256;
            const int r = cc >> 4, c4 = cc & 15;
            const float* s = &sm[r * PJ_CLD + c4 * 4];
            const int h = h0 + c4 * 4;
            float4 o;
            o.x = tf32r((s[0] + bias[h + 0]) * qs);
            o.y = tf32r((s[1] + bias[h + 1]) * qs);
            o.z = tf32r((s[2] + bias[h + 2]) * qs);
            o.w = tf32r((s[3] + bias[h + 3]) * qs);
            *(float4*)&out[(size_t)(m0 + r) * HID + h] = o;
        }
    } else {
        float* out_t = g_Vt + (size_t)b * HID * NB;
        #pragma unroll
        for (int hh = 0; hh < 8; hh++) {
            const int h = wid * 8 + hh;
            const float bb = bias[h0 + h];
            float4 o;
            o.x = tf32r(sm[(lane * 4 + 0) * PJ_CLD + h] + bb);
            o.y = tf32r(sm[(lane * 4 + 1) * PJ_CLD + h] + bb);
            o.z = tf32r(sm[(lane * 4 + 2) * PJ_CLD + h] + bb);
            o.w = tf32r(sm[(lane * 4 + 3) * PJ_CLD + h] + bb);
            *(float4*)&out_t[(size_t)(h0 + h) * NB + m0 + lane * 4] = o;
        }
    }
}

// ---------------- attention smem layout (float indices) ----------------
#define QLD 260
#define KLD 260
#define VLD 68
#define PLD 36
#define QS_F 0                        // 128 x 260 = 33280
#define KS_F 33280                    // 32 x 260  = 8320
#define VS_F 41600                    // 256 x 68  = 17408... (VLD=68 for 64-wide? no: FN=32)
// NOTE: FN=32 => V tile is 256 x 32, padded stride 36.
#undef VLD
#define VLD 36
#undef VS_F
#define VS_F 41600                    // 256 x 36 = 9216
#define PS_F 50816                    // 128 x 36 = 4608
#define MK_F 55424                    // 2048
#define LR_F 57472                    // 256
#define SMEM_FLOATS 57728
#define SMEM_BYTES  (SMEM_FLOATS * 4) // 230912 <= 232448

#define NTH 512

__device__ __forceinline__ void load_Qt(uint32_t smb, const float* Qb, int q0, int tid) {
    #pragma unroll
    for (int i = 0; i < 16; i++) {
        const int cc = tid + i * NTH;
        const int r = cc >> 6, c4 = cc & 63;
        cp16(smb + (QS_F + r * QLD + c4 * 4) * 4,
             Qb + (size_t)(q0 + r) * HID + c4 * 4);
    }
}
__device__ __forceinline__ void load_Kt(uint32_t smb, const float* Kb, int n0, int tid) {
    #pragma unroll
    for (int i = 0; i < 4; i++) {
        const int cc = tid + i * NTH;
        const int r = cc >> 6, c4 = cc & 63;
        cp16(smb + (KS_F + r * KLD + c4 * 4) * 4,
             Kb + (size_t)(n0 + r) * HID + c4 * 4);
    }
}
__device__ __forceinline__ void load_Vt(uint32_t smb, const float* Vtb, int n0, int tid) {
    #pragma unroll
    for (int i = 0; i < 4; i++) {
        const int cc = tid + i * NTH;
        const int h = cc >> 3, c4 = cc & 7;
        cp16(smb + (VS_F + h * VLD + c4 * 4) * 4,
             Vtb + (size_t)h * NB + n0 + c4 * 4);
    }
}

// ---------------- attention: 512 threads / 16 warps, 128 q rows / CTA ----------------
__global__ __launch_bounds__(NTH, 1) void attn_kernel(
    const int* __restrict__ maskB, float* __restrict__ out)
{
    extern __shared__ float sm[];
    const uint32_t smb = smem_u32(sm);

    const int tid  = threadIdx.x;
    const int lane = tid & 31;
    const int wid  = tid >> 5;
    const int mt   = wid & 7;    // m16 tile (8 tiles = 128 rows)
    const int nh   = wid >> 3;   // n-half(16) for S / h-half(128) for PV
    const int g    = lane >> 2;
    const int tg   = lane & 3;
    const int lsrow = (lane & 7) + 8 * (lane >> 4);
    const int lscol = 4 * ((lane >> 3) & 1);

    const int b  = blockIdx.y;
    const int q0 = blockIdx.x * FM;

    const float* Qb  = g_Q  + (size_t)b * NA * HID;
    const float* Kb  = g_K  + (size_t)b * NB * HID;
    const float* Vtb = g_Vt + (size_t)b * HID * NB;
    const int*   mk  = maskB + b * NB;

    for (int i = tid; i < NB; i += NTH) sm[MK_F + i] = (mk[i] != 0) ? 1.f : 0.f;

    // prologue: [Q + K0] group, then [V0] group
    load_Qt(smb, Qb, q0, tid);
    load_Kt(smb, Kb, 0, tid);              CP_COMMIT();
    load_Vt(smb, Vtb, 0, tid);             CP_COMMIT();

    const uint32_t aQ  = smb + (QS_F + (mt * 16 + lsrow) * QLD + lscol) * 4;
    const uint32_t bK  = smb + (KS_F + (nh * 16 + lsrow) * KLD + lscol) * 4;
    const uint32_t aP  = smb + (PS_F + (mt * 16 + lsrow) * PLD + lscol) * 4;
    const uint32_t bV  = smb + (VS_F + (nh * 128 + lsrow) * VLD + lscol) * 4;
    const uint32_t pw0 = smb + (PS_F + (mt * 16 + g) * PLD + nh * 16 + 2 * tg) * 4;

    float o[16][4];
    #pragma unroll
    for (int n = 0; n < 16; n++)
        #pragma unroll
        for (int j = 0; j < 4; j++) o[n][j] = 0.f;
    float lg = 0.f, lg8 = 0.f;

    for (int t = 0; t < NT; t++) {
        CP_WAIT(1);                 // K_t (and Q at t=0) resident
        __syncthreads();

        // ---- S = Q K_t^T : warp m16 x n16 ----
        float c[2][4] = {{0.f,0.f,0.f,0.f},{0.f,0.f,0.f,0.f}};
        #pragma unroll
        for (int ks = 0; ks < 32; ks++) {
            uint32_t a[4], bb[4];
            ldsm4(a, aQ + ks * 32);
            ldsm4(bb, bK + ks * 32);
            mma8(c[0], a, bb[0], bb[1]);
            mma8(c[1], a, bb[2], bb[3]);
        }

        // ---- exp (no-max) + mask, P -> smem ----
        const int n0 = t * FN;
        #pragma unroll
        for (int nb = 0; nb < 2; nb++) {
            const int col = n0 + nh * 16 + nb * 8 + 2 * tg;
            const float mv0 = sm[MK_F + col], mv1 = sm[MK_F + col + 1];
            const float e00 = __expf(c[nb][0]) * mv0;
            const float e01 = __expf(c[nb][1]) * mv1;
            const float e10 = __expf(c[nb][2]) * mv0;
            const float e11 = __expf(c[nb][3]) * mv1;
            lg  += e00 + e01;
            lg8 += e10 + e11;
            sts_v2(pw0 + nb * 32, tf32u(e00), tf32u(e01));
            sts_v2(pw0 + nb * 32 + 8 * PLD * 4, tf32u(e10), tf32u(e11));
        }
        __syncthreads();            // K consumed + P visible

        if (t + 1 < NT) load_Kt(smb, Kb, (t + 1) * FN, tid);
        CP_COMMIT();                // pending: [V_t, K_{t+1}]
        CP_WAIT(1);                 // V_t resident
        __syncthreads();

        // ---- O += P V_t : warp m16 x h128 ----
        #pragma unroll
        for (int ks = 0; ks < 4; ks++) {
            uint32_t a[4];
            ldsm4(a, aP + ks * 32);
            #pragma unroll
            for (int pr = 0; pr < 8; pr++) {
                uint32_t bb[4];
                ldsm4(bb, bV + pr * (16 * VLD * 4) + ks * 32);
                mma8(o[2 * pr + 0], a, bb[0], bb[1]);
                mma8(o[2 * pr + 1], a, bb[2], bb[3]);
            }
        }
        __syncthreads();            // V consumed

        if (t + 1 < NT) load_Vt(smb, Vtb, (t + 1) * FN, tid);
        CP_COMMIT();                // pending: [K_{t+1}, V_{t+1}]
    }

    // ---- l reduction: quad shuffle then cross-half via smem ----
    lg  += __shfl_xor_sync(0xffffffffu, lg, 1);
    lg  += __shfl_xor_sync(0xffffffffu, lg, 2);
    lg8 += __shfl_xor_sync(0xffffffffu, lg8, 1);
    lg8 += __shfl_xor_sync(0xffffffffu, lg8, 2);
    if (tg == 0) {
        sm[LR_F + nh * 128 + mt * 16 + g]     = lg;
        sm[LR_F + nh * 128 + mt * 16 + g + 8] = lg8;
    }
    __syncthreads();

    const int r0 = mt * 16 + g;
    const float inv0 = 1.f / (sm[LR_F + r0]     + sm[LR_F + 128 + r0]);
    const float inv8 = 1.f / (sm[LR_F + r0 + 8] + sm[LR_F + 128 + r0 + 8]);

    float* outb = out + ((size_t)b * NA + q0) * HID;
    #pragma unroll
    for (int nb = 0; nb < 16; nb++) {
        const int col = nh * 128 + nb * 8 + 2 * tg;
        float2 v0, v8;
        v0.x = o[nb][0] * inv0; v0.y = o[nb][1] * inv0;
        v8.x = o[nb][2] * inv8; v8.y = o[nb][3] * inv8;
        *(float2*)&outb[(size_t)(r0)     * HID + col] = v0;
        *(float2*)&outb[(size_t)(r0 + 8) * HID + col] = v8;
    }
}

// ---------------------------------------------------------------------------
extern "C" void kernel_launch(void* const* d_in, const int* in_sizes, int n_in,
                              void* d_out, int out_size)
{
    const float* A    = (const float*)d_in[0];
    const float* B    = (const float*)d_in[1];
    const int*   mask = (const int*)  d_in[2];
    const float* Wq   = (const float*)d_in[3];
    const float* bq   = (const float*)d_in[4];
    const float* Wk   = (const float*)d_in[5];
    const float* bk   = (const float*)d_in[6];
    const float* Wv   = (const float*)d_in[7];
    const float* bv   = (const float*)d_in[8];
    float* out = (float*)d_out;

    (void)in_sizes; (void)n_in; (void)out_size;

    cudaFuncSetAttribute(proj_kernel, cudaFuncAttributeMaxDynamicSharedMemorySize,
                         PJ_SMEM_BYTES);
    cudaFuncSetAttribute(attn_kernel, cudaFuncAttributeMaxDynamicSharedMemorySize,
                         SMEM_BYTES);

    round_kernel<<<1024, 256>>>(A, B, Wq, Wk, Wv);

    dim3 pg(NA / 128, HID / 64, 3 * BATCH);
    proj_kernel<<<pg, 256, PJ_SMEM_BYTES>>>(bq, bk, bv);

    dim3 ag(NA / FM, BATCH);
    attn_kernel<<<ag, NTH, SMEM_BYTES>>>(mask, out);
}